// round 1
// baseline (speedup 1.0000x reference)
#include <cuda_runtime.h>
#include <math.h>
#include <stdlib.h>

// Problem constants
#define B_ 16
#define C1_ 256
#define C2_ 256
#define H_ 64
#define W_ 64
#define NH_ 8
#define C_ 128          // C2/2
#define HD_ 16          // C/NH
#define HW_ (H_*W_)     // 4096
#define TOKENS (B_*HW_) // 65536

// -------- static scratch (allocations are forbidden at runtime) -----------
__device__ float g_xt  [(size_t)TOKENS*256]; // x transposed to [token, C1]
__device__ float g_cat [(size_t)TOKENS*384]; // [y1 y2 | f3] token-major, ld=384
__device__ float g_fn  [(size_t)TOKENS*128]; // LN output (reused)
__device__ float g_qkv [(size_t)TOKENS*384];
__device__ float g_attn[(size_t)TOKENS*128];
__device__ float g_f2  [(size_t)TOKENS*128];
__device__ float g_h1  [(size_t)TOKENS*256];

// ---------------------------------------------------------------------------
// NCHW -> [token, channel] transpose (per batch: [256,4096] -> [4096,256])
// ---------------------------------------------------------------------------
__global__ void transpose_x_kernel(const float* __restrict__ x,
                                   float* __restrict__ xt) {
    __shared__ float tile[32][33];
    int b  = blockIdx.z;
    int p0 = blockIdx.x * 32;   // pixel dim
    int c0 = blockIdx.y * 32;   // channel dim
    const float* xb = x  + (size_t)b * C1_ * HW_;
    float*      xtb = xt + (size_t)b * HW_ * C1_;
#pragma unroll
    for (int i = 0; i < 32; i += 8)
        tile[threadIdx.y + i][threadIdx.x] =
            xb[(size_t)(c0 + threadIdx.y + i) * HW_ + p0 + threadIdx.x];
    __syncthreads();
#pragma unroll
    for (int i = 0; i < 32; i += 8)
        xtb[(size_t)(p0 + threadIdx.y + i) * C1_ + c0 + threadIdx.x] =
            tile[threadIdx.x][threadIdx.y + i];
}

// ---------------------------------------------------------------------------
// Tiled SGEMM: C[M,N] = A[M,K] (row-major, lda) @ W[N,K]^T (row-major, ld=K)
// BM=BN=128, BK=8, 256 threads, 8x8 microtile. M=65536, N%128==0, K%8==0.
// Epilogue fused via template.
// ---------------------------------------------------------------------------
enum { EPI_BNSILU = 0, EPI_BIAS = 1, EPI_PROJ = 2, EPI_GELU = 3,
       EPI_BIASRES = 4, EPI_BNSILU_NCHW = 5 };

template <int EPI>
__global__ void __launch_bounds__(256)
gemm_nt(const float* __restrict__ A, int lda,
        const float* __restrict__ Wt, int K,
        float* __restrict__ Cp, int ldc,
        const float* __restrict__ p0, const float* __restrict__ p1,
        const float* __restrict__ p2, const float* __restrict__ p3,
        const float* __restrict__ Rs, int ldr) {
    __shared__ float As[8][128];
    __shared__ float Bs[8][128];

    const int tid  = threadIdx.x;
    const int arow = tid >> 1;          // 0..127
    const int acol = (tid & 1) * 4;     // 0 or 4
    const float* Ap = A  + (size_t)(blockIdx.x * 128 + arow) * lda + acol;
    const float* Bp = Wt + (size_t)(blockIdx.y * 128 + arow) * K   + acol;

    const int tr = (tid >> 4) * 8;      // row offset in tile
    const int tc = (tid & 15) * 8;      // col offset in tile

    float acc[8][8];
#pragma unroll
    for (int i = 0; i < 8; i++)
#pragma unroll
        for (int j = 0; j < 8; j++) acc[i][j] = 0.f;

    for (int k0 = 0; k0 < K; k0 += 8) {
        float4 av = *(const float4*)(Ap + k0);
        float4 bv = *(const float4*)(Bp + k0);
        As[acol + 0][arow] = av.x; As[acol + 1][arow] = av.y;
        As[acol + 2][arow] = av.z; As[acol + 3][arow] = av.w;
        Bs[acol + 0][arow] = bv.x; Bs[acol + 1][arow] = bv.y;
        Bs[acol + 2][arow] = bv.z; Bs[acol + 3][arow] = bv.w;
        __syncthreads();
#pragma unroll
        for (int k = 0; k < 8; k++) {
            float ra[8], rb[8];
#pragma unroll
            for (int i = 0; i < 8; i++) { ra[i] = As[k][tr + i]; rb[i] = Bs[k][tc + i]; }
#pragma unroll
            for (int i = 0; i < 8; i++)
#pragma unroll
                for (int j = 0; j < 8; j++) acc[i][j] += ra[i] * rb[j];
        }
        __syncthreads();
    }

    // Precompute per-column BN affine if needed
    float scj[8], shj[8];
    if (EPI == EPI_BNSILU || EPI == EPI_BNSILU_NCHW) {
#pragma unroll
        for (int j = 0; j < 8; j++) {
            int col = blockIdx.y * 128 + tc + j;
            float sc = p0[col] * rsqrtf(p3[col] + 1e-5f);
            scj[j] = sc;
            shj[j] = p1[col] - p2[col] * sc;
        }
    }

#pragma unroll
    for (int i = 0; i < 8; i++) {
        int row = blockIdx.x * 128 + tr + i;
#pragma unroll
        for (int j = 0; j < 8; j++) {
            int col = blockIdx.y * 128 + tc + j;
            float v = acc[i][j];
            if constexpr (EPI == EPI_BNSILU || EPI == EPI_BNSILU_NCHW) {
                v = v * scj[j] + shj[j];
                v = v / (1.f + expf(-v));                 // SiLU
            } else if constexpr (EPI == EPI_BIAS) {
                v += p0[col];
            } else if constexpr (EPI == EPI_PROJ) {
                v = Rs[(size_t)row * ldr + col] + (v + p0[col]) * p1[col];
            } else if constexpr (EPI == EPI_GELU) {
                v += p0[col];
                v = 0.5f * v * (1.f + erff(v * 0.70710678118654752f));
            } else if constexpr (EPI == EPI_BIASRES) {
                v = v + p0[col] + Rs[(size_t)row * ldr + col];
            }
            if constexpr (EPI == EPI_BNSILU_NCHW) {
                // row = b*4096 + hw ; write out[b, col, hw]
                Cp[(((size_t)(row >> 12) * C2_ + col) << 12) + (row & 4095)] = v;
            } else {
                Cp[(size_t)row * ldc + col] = v;
            }
        }
    }
}

// ---------------------------------------------------------------------------
// LayerNorm over last dim (128). One warp per token.
// ---------------------------------------------------------------------------
__global__ void ln_kernel(const float* __restrict__ in, int ld,
                          const float* __restrict__ g, const float* __restrict__ bb,
                          float* __restrict__ out) {
    int w    = threadIdx.x >> 5;
    int lane = threadIdx.x & 31;
    int t    = blockIdx.x * 8 + w;
    const float* row = in + (size_t)t * ld;
    float v[4];
    float s = 0.f;
#pragma unroll
    for (int i = 0; i < 4; i++) { v[i] = row[lane + 32 * i]; s += v[i]; }
#pragma unroll
    for (int o = 16; o; o >>= 1) s += __shfl_xor_sync(0xffffffffu, s, o);
    float mu = s * (1.f / 128.f);
    float q = 0.f;
#pragma unroll
    for (int i = 0; i < 4; i++) { float d = v[i] - mu; q += d * d; }
#pragma unroll
    for (int o = 16; o; o >>= 1) q += __shfl_xor_sync(0xffffffffu, q, o);
    float rs = rsqrtf(q * (1.f / 128.f) + 1e-5f);
#pragma unroll
    for (int i = 0; i < 4; i++) {
        int c = lane + 32 * i;
        out[(size_t)t * 128 + c] = (v[i] - mu) * rs * g[c] + bb[c];
    }
}

// ---------------------------------------------------------------------------
// Retention-style attention along H (ALONG_H=true) or W (false).
// One CTA per (b, head, fixed-col/row). 64 threads = the varying axis.
// out = 0.5*(out_h + out_w): H pass writes, W pass accumulates.
// ---------------------------------------------------------------------------
template <bool ALONG_H>
__global__ void attn_kernel(const float* __restrict__ qkv,
                            float* __restrict__ out) {
    int fixed = blockIdx.x;          // w if ALONG_H else h
    int n     = blockIdx.y;
    int b     = blockIdx.z;
    int t     = threadIdx.x;         // h if ALONG_H else w

    __shared__ float sk[64][16];
    __shared__ float sv[64][16];
    __shared__ float decrow[64];

    float dec = logf(1.f - exp2f(-2.f - 0.5f * (float)n));
    decrow[t] = expf(dec * (float)t);

    size_t tok = ALONG_H ? ((size_t)(b * 64 + t) * 64 + fixed)
                         : ((size_t)(b * 64 + fixed) * 64 + t);
    const float* base = qkv + tok * 384 + n * HD_;

    float qreg[16], o[16];
#pragma unroll
    for (int c = 0; c < 16; c++) {
        qreg[c]  = base[c];
        sk[t][c] = base[128 + c];
        sv[t][c] = base[256 + c];
        o[c] = 0.f;
    }
    __syncthreads();

    for (int j = 0; j < 64; j++) {
        float s = 0.f;
#pragma unroll
        for (int c = 0; c < 16; c++) s += qreg[c] * sk[j][c];
        s *= decrow[abs(t - j)];
#pragma unroll
        for (int c = 0; c < 16; c++) o[c] += s * sv[j][c];
    }

    float* op = out + tok * 128 + n * HD_;
    if (ALONG_H) {
#pragma unroll
        for (int c = 0; c < 16; c++) op[c] = 0.5f * o[c];
    } else {
#pragma unroll
        for (int c = 0; c < 16; c++) op[c] += 0.5f * o[c];
    }
}

// ---------------------------------------------------------------------------
extern "C" void kernel_launch(void* const* d_in, const int* in_sizes, int n_in,
                              void* d_out, int out_size) {
    const float* x      = (const float*)d_in[0];
    const float* cv1_w  = (const float*)d_in[1];
    const float* bn1_g  = (const float*)d_in[2];
    const float* bn1_b  = (const float*)d_in[3];
    const float* bn1_m  = (const float*)d_in[4];
    const float* bn1_v  = (const float*)d_in[5];
    const float* cv2_w  = (const float*)d_in[6];
    const float* bn2_g  = (const float*)d_in[7];
    const float* bn2_b  = (const float*)d_in[8];
    const float* bn2_m  = (const float*)d_in[9];
    const float* bn2_v  = (const float*)d_in[10];
    const float* ln1_g  = (const float*)d_in[11];
    const float* ln1_b  = (const float*)d_in[12];
    const float* qkv_w  = (const float*)d_in[13];
    const float* qkv_b  = (const float*)d_in[14];
    const float* proj_w = (const float*)d_in[15];
    const float* proj_b = (const float*)d_in[16];
    const float* gamma  = (const float*)d_in[17];
    const float* ln2_g  = (const float*)d_in[18];
    const float* ln2_b  = (const float*)d_in[19];
    const float* ffn_w1 = (const float*)d_in[20];
    const float* ffn_b1 = (const float*)d_in[21];
    const float* ffn_w2 = (const float*)d_in[22];
    const float* ffn_b2 = (const float*)d_in[23];
    float* out = (float*)d_out;

    float *xt, *cat, *fn, *qkv, *attn, *f2, *h1;
    cudaGetSymbolAddress((void**)&xt,   g_xt);
    cudaGetSymbolAddress((void**)&cat,  g_cat);
    cudaGetSymbolAddress((void**)&fn,   g_fn);
    cudaGetSymbolAddress((void**)&qkv,  g_qkv);
    cudaGetSymbolAddress((void**)&attn, g_attn);
    cudaGetSymbolAddress((void**)&f2,   g_f2);
    cudaGetSymbolAddress((void**)&h1,   g_h1);

    // 1) x NCHW -> xt [token, 256]
    transpose_x_kernel<<<dim3(HW_ / 32, C1_ / 32, B_), dim3(32, 8)>>>(x, xt);

    // 2) cv1 + BN + SiLU -> cat[:, 0:256]  (y1 | y2)
    gemm_nt<EPI_BNSILU><<<dim3(TOKENS / 128, 2), 256>>>(
        xt, 256, cv1_w, 256, cat, 384, bn1_g, bn1_b, bn1_m, bn1_v, nullptr, 0);

    // 3) LN1 on y2 = cat[:, 128:256]
    ln_kernel<<<TOKENS / 8, 256>>>(cat + 128, 384, ln1_g, ln1_b, fn);

    // 4) qkv = fn @ qkv_w^T + qkv_b
    gemm_nt<EPI_BIAS><<<dim3(TOKENS / 128, 3), 256>>>(
        fn, 128, qkv_w, 128, qkv, 384, qkv_b, nullptr, nullptr, nullptr, nullptr, 0);

    // 5) decay attention along H then W
    attn_kernel<true ><<<dim3(64, NH_, B_), 64>>>(qkv, attn);
    attn_kernel<false><<<dim3(64, NH_, B_), 64>>>(qkv, attn);

    // 6) f2 = y2 + (attn @ proj_w^T + proj_b) * gamma
    gemm_nt<EPI_PROJ><<<dim3(TOKENS / 128, 1), 256>>>(
        attn, 128, proj_w, 128, f2, 128, proj_b, gamma, nullptr, nullptr,
        cat + 128, 384);

    // 7) LN2
    ln_kernel<<<TOKENS / 8, 256>>>(f2, 128, ln2_g, ln2_b, fn);

    // 8) h1 = gelu(fn @ ffn_w1^T + ffn_b1)
    gemm_nt<EPI_GELU><<<dim3(TOKENS / 128, 2), 256>>>(
        fn, 128, ffn_w1, 128, h1, 256, ffn_b1, nullptr, nullptr, nullptr, nullptr, 0);

    // 9) cat[:, 256:384] = f2 + h1 @ ffn_w2^T + ffn_b2
    gemm_nt<EPI_BIASRES><<<dim3(TOKENS / 128, 1), 256>>>(
        h1, 256, ffn_w2, 256, cat + 256, 384, ffn_b2, nullptr, nullptr, nullptr,
        f2, 128);

    // 10) cv2 + BN + SiLU, written NCHW directly to d_out
    gemm_nt<EPI_BNSILU_NCHW><<<dim3(TOKENS / 128, 2), 256>>>(
        cat, 384, cv2_w, 384, out, 0, bn2_g, bn2_b, bn2_m, bn2_v, nullptr, 0);
}

// round 3
// speedup vs baseline: 2.4516x; 2.4516x over previous
#include <cuda_runtime.h>
#include <cuda_bf16.h>
#include <math.h>

// Problem constants
#define B_ 16
#define C1_ 256
#define C2_ 256
#define H_ 64
#define W_ 64
#define NH_ 8
#define C_ 128
#define HD_ 16
#define HW_ (H_*W_)
#define TOKENS (B_*HW_)

typedef unsigned int u32;

// -------- static scratch -----------
__device__ float g_xt  [(size_t)TOKENS*256];
__device__ float g_cat [(size_t)TOKENS*384];
__device__ float g_fn  [(size_t)TOKENS*128];
__device__ float g_qkv [(size_t)TOKENS*384];
__device__ float g_attn[(size_t)TOKENS*128];
__device__ float g_f2  [(size_t)TOKENS*128];
__device__ float g_h1  [(size_t)TOKENS*256];

// ---------------------------------------------------------------------------
// warp-level bf16 MMA: D += A(16x16) * B(16x8), fp32 accum
// ---------------------------------------------------------------------------
__device__ __forceinline__ void mma16816(float* c, const u32* a, const u32* b) {
    asm volatile(
        "mma.sync.aligned.m16n8k16.row.col.f32.bf16.bf16.f32 "
        "{%0,%1,%2,%3}, {%4,%5,%6,%7}, {%8,%9}, {%0,%1,%2,%3};"
        : "+f"(c[0]), "+f"(c[1]), "+f"(c[2]), "+f"(c[3])
        : "r"(a[0]), "r"(a[1]), "r"(a[2]), "r"(a[3]), "r"(b[0]), "r"(b[1]));
}

__device__ __forceinline__ u32 pack_hi_lo(float x, float y, u32& lo_out) {
    __nv_bfloat162 h = __float22bfloat162_rn(make_float2(x, y));
    float rx = x - __bfloat162float(h.x);
    float ry = y - __bfloat162float(h.y);
    __nv_bfloat162 l = __float22bfloat162_rn(make_float2(rx, ry));
    lo_out = *(u32*)&l;
    return *(u32*)&h;
}

// ---------------------------------------------------------------------------
// NCHW -> [token, channel] transpose
// ---------------------------------------------------------------------------
__global__ void transpose_x_kernel(const float* __restrict__ x,
                                   float* __restrict__ xt) {
    __shared__ float tile[32][33];
    int b  = blockIdx.z;
    int p0 = blockIdx.x * 32;
    int c0 = blockIdx.y * 32;
    const float* xb = x  + (size_t)b * C1_ * HW_;
    float*      xtb = xt + (size_t)b * HW_ * C1_;
#pragma unroll
    for (int i = 0; i < 32; i += 8)
        tile[threadIdx.y + i][threadIdx.x] =
            xb[(size_t)(c0 + threadIdx.y + i) * HW_ + p0 + threadIdx.x];
    __syncthreads();
#pragma unroll
    for (int i = 0; i < 32; i += 8)
        xtb[(size_t)(p0 + threadIdx.y + i) * C1_ + c0 + threadIdx.x] =
            tile[threadIdx.x][threadIdx.y + i];
}

// ---------------------------------------------------------------------------
// bf16 hi/lo 3-pass GEMM via mma.sync: C[M,N] = A[M,K] @ Wt[N,K]^T (fp32 io)
// Tile 128x128, BK=32, 256 thr (8 warps = 2m x 4n, warp tile 64x32).
// ---------------------------------------------------------------------------
enum { EPI_BNSILU = 0, EPI_BIAS = 1, EPI_PROJ = 2, EPI_GELU = 3,
       EPI_BIASRES = 4, EPI_BNSILU_NCHW = 5 };

#define TILE_U32   (128*20)              // one tile: 128 rows x 20 u32 (40 bf16)
#define SMEM_TILES (4*TILE_U32*4)        // 40960 B
#define SMEM_NCHW  (128*129*4)           // 66048 B staging
#define GSMEM_MAX  (SMEM_NCHW)

template <int EPI>
__global__ void __launch_bounds__(256)
gemm_mma(const float* __restrict__ A, int lda,
         const float* __restrict__ Wt, int K,
         float* __restrict__ Cp, int ldc,
         const float* __restrict__ p0, const float* __restrict__ p1,
         const float* __restrict__ p2, const float* __restrict__ p3,
         const float* __restrict__ Rs, int ldr) {
    extern __shared__ __align__(16) u32 smem_u[];
    u32* AHI = smem_u;
    u32* ALO = smem_u + TILE_U32;
    u32* BHI = smem_u + 2 * TILE_U32;
    u32* BLO = smem_u + 3 * TILE_U32;

    const int tid    = threadIdx.x;
    const int wid    = tid >> 5;
    const int lane   = tid & 31;
    const int warp_m = wid >> 2;        // 0..1
    const int warp_n = wid & 3;         // 0..3
    const int g      = lane >> 2;       // 0..7
    const int t2     = lane & 3;        // 0..3

    const int row0 = blockIdx.x * 128;
    const int col0 = blockIdx.y * 128;

    const int lrow = tid >> 3;          // 0..31
    const int lc4  = tid & 7;           // float4 column

    float acc[4][4][4];
#pragma unroll
    for (int i = 0; i < 4; i++)
#pragma unroll
        for (int j = 0; j < 4; j++)
#pragma unroll
            for (int q = 0; q < 4; q++) acc[i][j][q] = 0.f;

    const int nchunk = K >> 5;
    for (int c = 0; c < nchunk; c++) {
        // ---- load + fp32->bf16 hi/lo convert + store tiles ----
        const float* Abase = A  + (size_t)row0 * lda + c * 32;
        const float* Bbase = Wt + (size_t)col0 * K   + c * 32;
#pragma unroll
        for (int i = 0; i < 4; i++) {
            int r = lrow + i * 32;
            u32 o = r * 20 + lc4 * 2;
            float4 va = *(const float4*)(Abase + (size_t)r * lda + lc4 * 4);
            u32 l0, l1;
            u32 h0 = pack_hi_lo(va.x, va.y, l0);
            u32 h1 = pack_hi_lo(va.z, va.w, l1);
            AHI[o] = h0; AHI[o + 1] = h1;
            ALO[o] = l0; ALO[o + 1] = l1;
            float4 vb = *(const float4*)(Bbase + (size_t)r * K + lc4 * 4);
            h0 = pack_hi_lo(vb.x, vb.y, l0);
            h1 = pack_hi_lo(vb.z, vb.w, l1);
            BHI[o] = h0; BHI[o + 1] = h1;
            BLO[o] = l0; BLO[o + 1] = l1;
        }
        __syncthreads();

        // ---- two k16 steps ----
#pragma unroll
        for (int k16 = 0; k16 < 2; k16++) {
            const int ku = k16 * 8;
            u32 ah[4][4], al[4][4], bh[4][2], bl[4][2];
#pragma unroll
            for (int mf = 0; mf < 4; mf++) {
                int rbase = (warp_m * 64 + mf * 16 + g) * 20 + ku + t2;
                ah[mf][0] = AHI[rbase];
                ah[mf][1] = AHI[rbase + 160];
                ah[mf][2] = AHI[rbase + 4];
                ah[mf][3] = AHI[rbase + 164];
                al[mf][0] = ALO[rbase];
                al[mf][1] = ALO[rbase + 160];
                al[mf][2] = ALO[rbase + 4];
                al[mf][3] = ALO[rbase + 164];
            }
#pragma unroll
            for (int nf = 0; nf < 4; nf++) {
                int nbase = (warp_n * 32 + nf * 8 + g) * 20 + ku + t2;
                bh[nf][0] = BHI[nbase];
                bh[nf][1] = BHI[nbase + 4];
                bl[nf][0] = BLO[nbase];
                bl[nf][1] = BLO[nbase + 4];
            }
#pragma unroll
            for (int mf = 0; mf < 4; mf++)
#pragma unroll
                for (int nf = 0; nf < 4; nf++)
                    mma16816(acc[mf][nf], ah[mf], bh[nf]);
#pragma unroll
            for (int mf = 0; mf < 4; mf++)
#pragma unroll
                for (int nf = 0; nf < 4; nf++)
                    mma16816(acc[mf][nf], ah[mf], bl[nf]);
#pragma unroll
            for (int mf = 0; mf < 4; mf++)
#pragma unroll
                for (int nf = 0; nf < 4; nf++)
                    mma16816(acc[mf][nf], al[mf], bh[nf]);
        }
        __syncthreads();
    }

    // ---------------- epilogue ----------------
    if constexpr (EPI == EPI_BNSILU_NCHW) {
        // stage through smem, then coalesced NCHW writeout
        float* stg = (float*)smem_u;
#pragma unroll
        for (int mf = 0; mf < 4; mf++)
#pragma unroll
            for (int nf = 0; nf < 4; nf++) {
                int r = warp_m * 64 + mf * 16 + g;
                int cl = warp_n * 32 + nf * 8 + t2 * 2;
                stg[r * 129 + cl]           = acc[mf][nf][0];
                stg[r * 129 + cl + 1]       = acc[mf][nf][1];
                stg[(r + 8) * 129 + cl]     = acc[mf][nf][2];
                stg[(r + 8) * 129 + cl + 1] = acc[mf][nf][3];
            }
        __syncthreads();
        for (int it = 0; it < 64; it++) {
            int idx  = it * 256 + tid;
            int lcol = idx >> 7;
            int r    = idx & 127;
            int col  = col0 + lcol;
            int row  = row0 + r;
            float v  = stg[r * 129 + lcol];
            float sc = p0[col] * rsqrtf(p3[col] + 1e-5f);
            v = v * sc + (p1[col] - p2[col] * sc);
            v = v / (1.f + expf(-v));
            Cp[(((size_t)(row >> 12)) * C2_ + col) * 4096 + (row & 4095)] = v;
        }
    } else {
        // register epilogue, float2 stores
#pragma unroll
        for (int mf = 0; mf < 4; mf++) {
            int row = row0 + warp_m * 64 + mf * 16 + g;
#pragma unroll
            for (int nf = 0; nf < 4; nf++) {
                int col = col0 + warp_n * 32 + nf * 8 + t2 * 2;
                float pr0 = 0.f, pr1 = 0.f;   // per-col epi params
                float ps0 = 0.f, ps1 = 0.f;
                if constexpr (EPI == EPI_BNSILU) {
                    pr0 = p0[col]   * rsqrtf(p3[col]   + 1e-5f);
                    pr1 = p0[col+1] * rsqrtf(p3[col+1] + 1e-5f);
                    ps0 = p1[col]   - p2[col]   * pr0;
                    ps1 = p1[col+1] - p2[col+1] * pr1;
                } else if constexpr (EPI == EPI_PROJ) {
                    pr0 = p0[col]; pr1 = p0[col+1];
                    ps0 = p1[col]; ps1 = p1[col+1];
                } else if constexpr (EPI == EPI_BIAS || EPI == EPI_GELU ||
                                     EPI == EPI_BIASRES) {
                    pr0 = p0[col]; pr1 = p0[col+1];
                }
#pragma unroll
                for (int half = 0; half < 2; half++) {
                    int rr = row + half * 8;
                    float v0 = acc[mf][nf][half * 2];
                    float v1 = acc[mf][nf][half * 2 + 1];
                    if constexpr (EPI == EPI_BNSILU) {
                        v0 = v0 * pr0 + ps0; v0 = v0 / (1.f + expf(-v0));
                        v1 = v1 * pr1 + ps1; v1 = v1 / (1.f + expf(-v1));
                    } else if constexpr (EPI == EPI_BIAS) {
                        v0 += pr0; v1 += pr1;
                    } else if constexpr (EPI == EPI_PROJ) {
                        float2 rs = *(const float2*)(Rs + (size_t)rr * ldr + col);
                        v0 = rs.x + (v0 + pr0) * ps0;
                        v1 = rs.y + (v1 + pr1) * ps1;
                    } else if constexpr (EPI == EPI_GELU) {
                        v0 += pr0; v1 += pr1;
                        v0 = 0.5f * v0 * (1.f + erff(v0 * 0.70710678118654752f));
                        v1 = 0.5f * v1 * (1.f + erff(v1 * 0.70710678118654752f));
                    } else if constexpr (EPI == EPI_BIASRES) {
                        float2 rs = *(const float2*)(Rs + (size_t)rr * ldr + col);
                        v0 = v0 + pr0 + rs.x;
                        v1 = v1 + pr1 + rs.y;
                    }
                    *(float2*)(Cp + (size_t)rr * ldc + col) = make_float2(v0, v1);
                }
            }
        }
    }
}

// ---------------------------------------------------------------------------
// LayerNorm over last dim (128). One warp per token.
// ---------------------------------------------------------------------------
__global__ void ln_kernel(const float* __restrict__ in, int ld,
                          const float* __restrict__ g, const float* __restrict__ bb,
                          float* __restrict__ out) {
    int w    = threadIdx.x >> 5;
    int lane = threadIdx.x & 31;
    int t    = blockIdx.x * 8 + w;
    const float* row = in + (size_t)t * ld;
    float v[4];
    float s = 0.f;
#pragma unroll
    for (int i = 0; i < 4; i++) { v[i] = row[lane + 32 * i]; s += v[i]; }
#pragma unroll
    for (int o = 16; o; o >>= 1) s += __shfl_xor_sync(0xffffffffu, s, o);
    float mu = s * (1.f / 128.f);
    float q = 0.f;
#pragma unroll
    for (int i = 0; i < 4; i++) { float d = v[i] - mu; q += d * d; }
#pragma unroll
    for (int o = 16; o; o >>= 1) q += __shfl_xor_sync(0xffffffffu, q, o);
    float rs = rsqrtf(q * (1.f / 128.f) + 1e-5f);
#pragma unroll
    for (int i = 0; i < 4; i++) {
        int c = lane + 32 * i;
        out[(size_t)t * 128 + c] = (v[i] - mu) * rs * g[c] + bb[c];
    }
}

// ---------------------------------------------------------------------------
// Retention attention (float4-vectorized). One CTA per (b, head, fixed).
// ---------------------------------------------------------------------------
template <bool ALONG_H>
__global__ void attn_kernel(const float* __restrict__ qkv,
                            float* __restrict__ out) {
    int fixed = blockIdx.x;
    int n     = blockIdx.y;
    int b     = blockIdx.z;
    int t     = threadIdx.x;

    __shared__ float4 sk4[64][4];
    __shared__ float4 sv4[64][4];
    __shared__ float  decrow[64];

    float dec = logf(1.f - exp2f(-2.f - 0.5f * (float)n));
    decrow[t] = expf(dec * (float)t);

    size_t tok = ALONG_H ? ((size_t)(b * 64 + t) * 64 + fixed)
                         : ((size_t)(b * 64 + fixed) * 64 + t);
    const float4* base = (const float4*)(qkv + tok * 384 + n * HD_);

    float4 q0 = base[0], q1 = base[1], q2 = base[2], q3 = base[3];
    sk4[t][0] = base[32]; sk4[t][1] = base[33];
    sk4[t][2] = base[34]; sk4[t][3] = base[35];
    sv4[t][0] = base[64]; sv4[t][1] = base[65];
    sv4[t][2] = base[66]; sv4[t][3] = base[67];
    float4 o0 = {0,0,0,0}, o1 = {0,0,0,0}, o2 = {0,0,0,0}, o3 = {0,0,0,0};
    __syncthreads();

#pragma unroll 4
    for (int j = 0; j < 64; j++) {
        float4 k0 = sk4[j][0], k1 = sk4[j][1], k2 = sk4[j][2], k3 = sk4[j][3];
        float s = q0.x*k0.x + q0.y*k0.y + q0.z*k0.z + q0.w*k0.w
                + q1.x*k1.x + q1.y*k1.y + q1.z*k1.z + q1.w*k1.w
                + q2.x*k2.x + q2.y*k2.y + q2.z*k2.z + q2.w*k2.w
                + q3.x*k3.x + q3.y*k3.y + q3.z*k3.z + q3.w*k3.w;
        s *= decrow[abs(t - j)];
        float4 v0 = sv4[j][0], v1 = sv4[j][1], v2 = sv4[j][2], v3 = sv4[j][3];
        o0.x += s*v0.x; o0.y += s*v0.y; o0.z += s*v0.z; o0.w += s*v0.w;
        o1.x += s*v1.x; o1.y += s*v1.y; o1.z += s*v1.z; o1.w += s*v1.w;
        o2.x += s*v2.x; o2.y += s*v2.y; o2.z += s*v2.z; o2.w += s*v2.w;
        o3.x += s*v3.x; o3.y += s*v3.y; o3.z += s*v3.z; o3.w += s*v3.w;
    }

    float4* op = (float4*)(out + tok * 128 + n * HD_);
    if (ALONG_H) {
        op[0] = make_float4(0.5f*o0.x, 0.5f*o0.y, 0.5f*o0.z, 0.5f*o0.w);
        op[1] = make_float4(0.5f*o1.x, 0.5f*o1.y, 0.5f*o1.z, 0.5f*o1.w);
        op[2] = make_float4(0.5f*o2.x, 0.5f*o2.y, 0.5f*o2.z, 0.5f*o2.w);
        op[3] = make_float4(0.5f*o3.x, 0.5f*o3.y, 0.5f*o3.z, 0.5f*o3.w);
    } else {
        float4 c0 = op[0], c1 = op[1], c2 = op[2], c3 = op[3];
        op[0] = make_float4(c0.x + 0.5f*o0.x, c0.y + 0.5f*o0.y, c0.z + 0.5f*o0.z, c0.w + 0.5f*o0.w);
        op[1] = make_float4(c1.x + 0.5f*o1.x, c1.y + 0.5f*o1.y, c1.z + 0.5f*o1.z, c1.w + 0.5f*o1.w);
        op[2] = make_float4(c2.x + 0.5f*o2.x, c2.y + 0.5f*o2.y, c2.z + 0.5f*o2.z, c2.w + 0.5f*o2.w);
        op[3] = make_float4(c3.x + 0.5f*o3.x, c3.y + 0.5f*o3.y, c3.z + 0.5f*o3.z, c3.w + 0.5f*o3.w);
    }
}

// ---------------------------------------------------------------------------
extern "C" void kernel_launch(void* const* d_in, const int* in_sizes, int n_in,
                              void* d_out, int out_size) {
    const float* x      = (const float*)d_in[0];
    const float* cv1_w  = (const float*)d_in[1];
    const float* bn1_g  = (const float*)d_in[2];
    const float* bn1_b  = (const float*)d_in[3];
    const float* bn1_m  = (const float*)d_in[4];
    const float* bn1_v  = (const float*)d_in[5];
    const float* cv2_w  = (const float*)d_in[6];
    const float* bn2_g  = (const float*)d_in[7];
    const float* bn2_b  = (const float*)d_in[8];
    const float* bn2_m  = (const float*)d_in[9];
    const float* bn2_v  = (const float*)d_in[10];
    const float* ln1_g  = (const float*)d_in[11];
    const float* ln1_b  = (const float*)d_in[12];
    const float* qkv_w  = (const float*)d_in[13];
    const float* qkv_b  = (const float*)d_in[14];
    const float* proj_w = (const float*)d_in[15];
    const float* proj_b = (const float*)d_in[16];
    const float* gamma  = (const float*)d_in[17];
    const float* ln2_g  = (const float*)d_in[18];
    const float* ln2_b  = (const float*)d_in[19];
    const float* ffn_w1 = (const float*)d_in[20];
    const float* ffn_b1 = (const float*)d_in[21];
    const float* ffn_w2 = (const float*)d_in[22];
    const float* ffn_b2 = (const float*)d_in[23];
    float* out = (float*)d_out;

    float *xt, *cat, *fn, *qkv, *attn, *f2, *h1;
    cudaGetSymbolAddress((void**)&xt,   g_xt);
    cudaGetSymbolAddress((void**)&cat,  g_cat);
    cudaGetSymbolAddress((void**)&fn,   g_fn);
    cudaGetSymbolAddress((void**)&qkv,  g_qkv);
    cudaGetSymbolAddress((void**)&attn, g_attn);
    cudaGetSymbolAddress((void**)&f2,   g_f2);
    cudaGetSymbolAddress((void**)&h1,   g_h1);

    cudaFuncSetAttribute(gemm_mma<EPI_BNSILU_NCHW>,
                         cudaFuncAttributeMaxDynamicSharedMemorySize, GSMEM_MAX);

    // 1) x NCHW -> xt [token, 256]
    transpose_x_kernel<<<dim3(HW_ / 32, C1_ / 32, B_), dim3(32, 8)>>>(x, xt);

    // 2) cv1 + BN + SiLU -> cat[:, 0:256]
    gemm_mma<EPI_BNSILU><<<dim3(TOKENS / 128, 2), 256, SMEM_TILES>>>(
        xt, 256, cv1_w, 256, cat, 384, bn1_g, bn1_b, bn1_m, bn1_v, nullptr, 0);

    // 3) LN1 on y2 = cat[:, 128:256]
    ln_kernel<<<TOKENS / 8, 256>>>(cat + 128, 384, ln1_g, ln1_b, fn);

    // 4) qkv = fn @ qkv_w^T + qkv_b
    gemm_mma<EPI_BIAS><<<dim3(TOKENS / 128, 3), 256, SMEM_TILES>>>(
        fn, 128, qkv_w, 128, qkv, 384, qkv_b, nullptr, nullptr, nullptr, nullptr, 0);

    // 5) decay attention along H then W
    attn_kernel<true ><<<dim3(64, NH_, B_), 64>>>(qkv, attn);
    attn_kernel<false><<<dim3(64, NH_, B_), 64>>>(qkv, attn);

    // 6) f2 = y2 + (attn @ proj_w^T + proj_b) * gamma
    gemm_mma<EPI_PROJ><<<dim3(TOKENS / 128, 1), 256, SMEM_TILES>>>(
        attn, 128, proj_w, 128, f2, 128, proj_b, gamma, nullptr, nullptr,
        cat + 128, 384);

    // 7) LN2
    ln_kernel<<<TOKENS / 8, 256>>>(f2, 128, ln2_g, ln2_b, fn);

    // 8) h1 = gelu(fn @ ffn_w1^T + ffn_b1)
    gemm_mma<EPI_GELU><<<dim3(TOKENS / 128, 2), 256, SMEM_TILES>>>(
        fn, 128, ffn_w1, 128, h1, 256, ffn_b1, nullptr, nullptr, nullptr, nullptr, 0);

    // 9) cat[:, 256:384] = f2 + h1 @ ffn_w2^T + ffn_b2
    gemm_mma<EPI_BIASRES><<<dim3(TOKENS / 128, 1), 256, SMEM_TILES>>>(
        h1, 256, ffn_w2, 256, cat + 256, 384, ffn_b2, nullptr, nullptr, nullptr,
        f2, 128);

    // 10) cv2 + BN + SiLU, written NCHW directly to d_out
    gemm_mma<EPI_BNSILU_NCHW><<<dim3(TOKENS / 128, 2), 256, GSMEM_MAX>>>(
        cat, 384, cv2_w, 384, out, 0, bn2_g, bn2_b, bn2_m, bn2_v, nullptr, 0);
}

// round 4
// speedup vs baseline: 4.5271x; 1.8466x over previous
#include <cuda_runtime.h>
#include <cuda_fp16.h>
#include <math.h>

#define B_ 16
#define C1_ 256
#define C2_ 256
#define H_ 64
#define W_ 64
#define NH_ 8
#define C_ 128
#define HD_ 16
#define HW_ (H_*W_)
#define TOKENS (B_*HW_)

typedef unsigned int u32;

// -------- static scratch -----------
__device__ __half g_xt16  [(size_t)TOKENS*256];
__device__ __half g_cat16 [(size_t)TOKENS*384];
__device__ float  g_y2f   [(size_t)TOKENS*128];
__device__ __half g_fn16  [(size_t)TOKENS*128];
__device__ __half g_qkv16 [(size_t)TOKENS*384];
__device__ float  g_attnp [(size_t)TOKENS*128];
__device__ __half g_attn16[(size_t)TOKENS*128];
__device__ float  g_f2    [(size_t)TOKENS*128];
__device__ __half g_h116  [(size_t)TOKENS*256];
// weights fp16: cv1 65536 | qkv 49152 | proj 16384 | ffn1 32768 | ffn2 32768 | cv2 98304
__device__ __half g_w16[65536+49152+16384+32768+32768+98304];

// ---------------------------------------------------------------------------
__device__ __forceinline__ u32 smem_u32(const void* p) {
    u32 a;
    asm("{ .reg .u64 t; cvta.to.shared.u64 t, %1; cvt.u32.u64 %0, t; }"
        : "=r"(a) : "l"(p));
    return a;
}
__device__ __forceinline__ void mma_fp16(float* c, const u32* a, const u32* b) {
    asm volatile(
        "mma.sync.aligned.m16n8k16.row.col.f32.f16.f16.f32 "
        "{%0,%1,%2,%3}, {%4,%5,%6,%7}, {%8,%9}, {%0,%1,%2,%3};"
        : "+f"(c[0]), "+f"(c[1]), "+f"(c[2]), "+f"(c[3])
        : "r"(a[0]), "r"(a[1]), "r"(a[2]), "r"(a[3]), "r"(b[0]), "r"(b[1]));
}
__device__ __forceinline__ void ldm_x4(u32& r0, u32& r1, u32& r2, u32& r3, u32 a) {
    asm volatile("ldmatrix.sync.aligned.m8n8.x4.shared.b16 {%0,%1,%2,%3}, [%4];"
        : "=r"(r0), "=r"(r1), "=r"(r2), "=r"(r3) : "r"(a));
}
__device__ __forceinline__ void ldm_x4t(u32& r0, u32& r1, u32& r2, u32& r3, u32 a) {
    asm volatile("ldmatrix.sync.aligned.m8n8.x4.trans.shared.b16 {%0,%1,%2,%3}, [%4];"
        : "=r"(r0), "=r"(r1), "=r"(r2), "=r"(r3) : "r"(a));
}
__device__ __forceinline__ void cp16(u32 dst, const void* src) {
    asm volatile("cp.async.cg.shared.global [%0], [%1], 16;" :: "r"(dst), "l"(src));
}

// ---------------------------------------------------------------------------
// weight fp32 -> fp16
__global__ void convert_w_kernel(const float* __restrict__ src,
                                 __half* __restrict__ dst, int n2) {
    int i = blockIdx.x * 256 + threadIdx.x;
    if (i < n2) {
        float2 v = *(const float2*)(src + 2 * i);
        *(__half2*)(dst + 2 * i) = __floats2half2_rn(v.x, v.y);
    }
}

// NCHW -> [token, channel] fp16 transpose
__global__ void transpose_x_kernel(const float* __restrict__ x,
                                   __half* __restrict__ xt) {
    __shared__ float tile[32][33];
    int b  = blockIdx.z;
    int p0 = blockIdx.x * 32;
    int c0 = blockIdx.y * 32;
    const float* xb = x + (size_t)b * C1_ * HW_;
    __half*     xtb = xt + (size_t)b * HW_ * C1_;
#pragma unroll
    for (int i = 0; i < 32; i += 8)
        tile[threadIdx.y + i][threadIdx.x] =
            xb[(size_t)(c0 + threadIdx.y + i) * HW_ + p0 + threadIdx.x];
    __syncthreads();
#pragma unroll
    for (int i = 0; i < 32; i += 8)
        xtb[(size_t)(p0 + threadIdx.y + i) * C1_ + c0 + threadIdx.x] =
            __float2half_rn(tile[threadIdx.x][threadIdx.y + i]);
}

// ---------------------------------------------------------------------------
// fp16 GEMM: C[M,N] = A[M,K] @ Wt[N,K]^T.  CTA 128x128, 4 warps (2x2) of 64x64.
// BK=64, double-buffered cp.async, ldmatrix fragments. smem rows padded 144B.
// ---------------------------------------------------------------------------
enum { EPI_CV1 = 0, EPI_QKV = 1, EPI_PROJ = 2, EPI_GELU = 3,
       EPI_FFN2 = 4, EPI_NCHW = 5 };

#define STG_BYTES 36864              // one stage: A(18432)+B(18432)
#define GSMEM_BYTES (2*STG_BYTES)    // 73728

template <int EPI>
__global__ void __launch_bounds__(128)
gemm_fp16(const __half* __restrict__ A, int lda,
          const __half* __restrict__ Wt, int K,
          void* __restrict__ Cpv, int ldc,
          const float* __restrict__ p0, const float* __restrict__ p1,
          const float* __restrict__ p2, const float* __restrict__ p3,
          const float* __restrict__ Rs, int ldr) {
    extern __shared__ __align__(16) char smem[];
    const u32 sb = smem_u32(smem);
    const int tid = threadIdx.x, wid = tid >> 5, lane = tid & 31;
    const int wm = (wid >> 1) * 64, wn = (wid & 1) * 64;
    const int g = lane >> 2, t2 = lane & 3;
    const int row0 = blockIdx.x * 128, col0 = blockIdx.y * 128;
    const int lrow = tid >> 3, lc8 = tid & 7;

    float acc[4][8][4];
#pragma unroll
    for (int i = 0; i < 4; i++)
#pragma unroll
        for (int j = 0; j < 8; j++)
#pragma unroll
            for (int q = 0; q < 4; q++) acc[i][j][q] = 0.f;

    const int nch = K >> 6;
    auto issue = [&](int c) {
        u32 ab = sb + (c & 1) * STG_BYTES;
        u32 bb = ab + 18432;
        const __half* Ag = A  + (size_t)row0 * lda + c * 64;
        const __half* Bg = Wt + (size_t)col0 * K   + c * 64;
#pragma unroll
        for (int i = 0; i < 8; i++) {
            int r = i * 16 + lrow;
            cp16(ab + r * 144 + lc8 * 16, Ag + (size_t)r * lda + lc8 * 8);
            cp16(bb + r * 144 + lc8 * 16, Bg + (size_t)r * K   + lc8 * 8);
        }
    };

    issue(0);
    asm volatile("cp.async.commit_group;");
    for (int c = 0; c < nch; c++) {
        if (c + 1 < nch) {
            issue(c + 1);
            asm volatile("cp.async.commit_group;");
            asm volatile("cp.async.wait_group 1;");
        } else {
            asm volatile("cp.async.wait_group 0;");
        }
        __syncthreads();
        u32 ab = sb + (c & 1) * STG_BYTES;
        u32 bb = ab + 18432;
#pragma unroll
        for (int kb = 0; kb < 4; kb++) {
            u32 a[4][4], b[8][2];
#pragma unroll
            for (int mf = 0; mf < 4; mf++) {
                int r = wm + mf * 16 + (lane & 7) + ((lane >> 3) & 1) * 8;
                ldm_x4(a[mf][0], a[mf][1], a[mf][2], a[mf][3],
                       ab + r * 144 + kb * 32 + (lane >> 4) * 16);
            }
#pragma unroll
            for (int np = 0; np < 4; np++) {
                int r = wn + np * 16 + (lane & 7) + ((lane >> 4) & 1) * 8;
                ldm_x4(b[2*np][0], b[2*np][1], b[2*np+1][0], b[2*np+1][1],
                       bb + r * 144 + kb * 32 + ((lane >> 3) & 1) * 16);
            }
#pragma unroll
            for (int mf = 0; mf < 4; mf++)
#pragma unroll
                for (int nf = 0; nf < 8; nf++)
                    mma_fp16(acc[mf][nf], a[mf], b[nf]);
        }
        __syncthreads();
    }

    // ------------- epilogue -------------
    if constexpr (EPI == EPI_NCHW) {
        float* stg = (float*)smem;   // 128x129
#pragma unroll
        for (int mf = 0; mf < 4; mf++)
#pragma unroll
            for (int nf = 0; nf < 8; nf++) {
                int r = wm + mf * 16 + g;
                int cl = wn + nf * 8 + t2 * 2;
                stg[r * 129 + cl]           = acc[mf][nf][0];
                stg[r * 129 + cl + 1]       = acc[mf][nf][1];
                stg[(r + 8) * 129 + cl]     = acc[mf][nf][2];
                stg[(r + 8) * 129 + cl + 1] = acc[mf][nf][3];
            }
        __syncthreads();
        float* Cp = (float*)Cpv;
        for (int it = 0; it < 128; it++) {
            int idx  = it * 128 + tid;
            int lcol = idx >> 7;
            int r    = idx & 127;
            int col  = col0 + lcol;
            int row  = row0 + r;
            float v  = stg[r * 129 + lcol];
            float sc = p0[col] * rsqrtf(p3[col] + 1e-5f);
            v = v * sc + (p1[col] - p2[col] * sc);
            v = v / (1.f + expf(-v));
            Cp[(((size_t)(row >> 12)) * C2_ + col) * 4096 + (row & 4095)] = v;
        }
    } else {
#pragma unroll
        for (int mf = 0; mf < 4; mf++) {
#pragma unroll
            for (int nf = 0; nf < 8; nf++) {
                int col = col0 + wn + nf * 8 + t2 * 2;
                float e0 = 0.f, e1 = 0.f, f0 = 0.f, f1 = 0.f;
                if constexpr (EPI == EPI_CV1) {
                    e0 = p0[col]     * rsqrtf(p3[col]     + 1e-5f);
                    e1 = p0[col + 1] * rsqrtf(p3[col + 1] + 1e-5f);
                    f0 = p1[col]     - p2[col]     * e0;
                    f1 = p1[col + 1] - p2[col + 1] * e1;
                } else if constexpr (EPI == EPI_PROJ) {
                    e0 = p0[col]; e1 = p0[col + 1];
                    f0 = p1[col]; f1 = p1[col + 1];
                } else {
                    e0 = p0[col]; e1 = p0[col + 1];
                }
#pragma unroll
                for (int h = 0; h < 2; h++) {
                    int row = row0 + wm + mf * 16 + g + h * 8;
                    float v0 = acc[mf][nf][h * 2];
                    float v1 = acc[mf][nf][h * 2 + 1];
                    if constexpr (EPI == EPI_CV1) {
                        v0 = v0 * e0 + f0; v0 = v0 / (1.f + expf(-v0));
                        v1 = v1 * e1 + f1; v1 = v1 / (1.f + expf(-v1));
                        __half* Cp = (__half*)Cpv;
                        *(__half2*)(Cp + (size_t)row * 384 + col) =
                            __floats2half2_rn(v0, v1);
                        if (col >= 128)
                            *(float2*)(Rs ? nullptr : nullptr, g_y2f +
                                       (size_t)row * 128 + col - 128) =
                                make_float2(v0, v1);
                    } else if constexpr (EPI == EPI_QKV) {
                        v0 += e0; v1 += e1;
                        __half* Cp = (__half*)Cpv;
                        *(__half2*)(Cp + (size_t)row * ldc + col) =
                            __floats2half2_rn(v0, v1);
                    } else if constexpr (EPI == EPI_PROJ) {
                        float2 rs = *(const float2*)(Rs + (size_t)row * ldr + col);
                        v0 = rs.x + (v0 + e0) * f0;
                        v1 = rs.y + (v1 + e1) * f1;
                        *(float2*)((float*)Cpv + (size_t)row * ldc + col) =
                            make_float2(v0, v1);
                    } else if constexpr (EPI == EPI_GELU) {
                        v0 += e0; v1 += e1;
                        v0 = 0.5f * v0 * (1.f + erff(v0 * 0.70710678118654752f));
                        v1 = 0.5f * v1 * (1.f + erff(v1 * 0.70710678118654752f));
                        *(__half2*)((__half*)Cpv + (size_t)row * ldc + col) =
                            __floats2half2_rn(v0, v1);
                    } else if constexpr (EPI == EPI_FFN2) {
                        float2 rs = *(const float2*)(Rs + (size_t)row * ldr + col);
                        v0 = v0 + e0 + rs.x;
                        v1 = v1 + e1 + rs.y;
                        *(__half2*)((__half*)Cpv + (size_t)row * ldc + col) =
                            __floats2half2_rn(v0, v1);
                    }
                }
            }
        }
    }
}

// ---------------------------------------------------------------------------
// LayerNorm (fp32 in, fp16 out). One warp per token.
// ---------------------------------------------------------------------------
__global__ void ln_kernel(const float* __restrict__ in, int ld,
                          const float* __restrict__ g, const float* __restrict__ bb,
                          __half* __restrict__ out) {
    int w    = threadIdx.x >> 5;
    int lane = threadIdx.x & 31;
    int t    = blockIdx.x * 8 + w;
    const float* row = in + (size_t)t * ld;
    float v[4];
    float s = 0.f;
#pragma unroll
    for (int i = 0; i < 4; i++) { v[i] = row[lane + 32 * i]; s += v[i]; }
#pragma unroll
    for (int o = 16; o; o >>= 1) s += __shfl_xor_sync(0xffffffffu, s, o);
    float mu = s * (1.f / 128.f);
    float q = 0.f;
#pragma unroll
    for (int i = 0; i < 4; i++) { float d = v[i] - mu; q += d * d; }
#pragma unroll
    for (int o = 16; o; o >>= 1) q += __shfl_xor_sync(0xffffffffu, q, o);
    float rs = rsqrtf(q * (1.f / 128.f) + 1e-5f);
#pragma unroll
    for (int i = 0; i < 4; i++) {
        int c = lane + 32 * i;
        out[(size_t)t * 128 + c] =
            __float2half_rn((v[i] - mu) * rs * g[c] + bb[c]);
    }
}

// ---------------------------------------------------------------------------
// Tensor-core retention attention. One warp per (b, head, fixed line).
// PASS 0: along H, writes fp32 partial. PASS 1: along W, adds, writes fp16.
// ---------------------------------------------------------------------------
template <int PASS>
__global__ void __launch_bounds__(128)
attn_mma(const __half* __restrict__ qkv,
         float* __restrict__ partial,
         __half* __restrict__ out16) {
    __shared__ __half sQ[4][64 * 24];
    __shared__ __half sK[4][64 * 24];
    __shared__ __half sV[4][64 * 24];
    __shared__ float decrow[64];

    const int tid = threadIdx.x, wid = tid >> 5, lane = tid & 31;
    const int g = lane >> 2, t2 = lane & 3;
    const int fixed = blockIdx.x * 4 + wid;
    const int n = blockIdx.y, b = blockIdx.z;

    if (tid < 64) {
        float dec = logf(1.f - exp2f(-2.f - 0.5f * (float)n));
        decrow[tid] = 0.5f * expf(dec * (float)tid);
    }

#pragma unroll
    for (int tt = 0; tt < 2; tt++) {
        int t = lane + tt * 32;
        size_t tok = (PASS == 0) ? ((size_t)(b * 64 + t) * 64 + fixed)
                                 : ((size_t)(b * 64 + fixed) * 64 + t);
        const uint4* src = (const uint4*)(qkv + tok * 384 + n * HD_);
        *(uint4*)&sQ[wid][t * 24]     = src[0];
        *(uint4*)&sQ[wid][t * 24 + 8] = src[1];
        *(uint4*)&sK[wid][t * 24]     = src[16];
        *(uint4*)&sK[wid][t * 24 + 8] = src[17];
        *(uint4*)&sV[wid][t * 24]     = src[32];
        *(uint4*)&sV[wid][t * 24 + 8] = src[33];
    }
    __syncthreads();

    const u32 qb = smem_u32(&sQ[wid][0]);
    const u32 kb = smem_u32(&sK[wid][0]);
    const u32 vb = smem_u32(&sV[wid][0]);

    // Q fragments (rows = tokens, k = 16 channels)
    u32 qa[4][4];
#pragma unroll
    for (int mf = 0; mf < 4; mf++) {
        int r = mf * 16 + (lane & 7) + ((lane >> 3) & 1) * 8;
        ldm_x4(qa[mf][0], qa[mf][1], qa[mf][2], qa[mf][3],
               qb + r * 48 + (lane >> 4) * 16);
    }

    float oacc[4][2][4];
#pragma unroll
    for (int i = 0; i < 4; i++)
#pragma unroll
        for (int j = 0; j < 2; j++)
#pragma unroll
            for (int q = 0; q < 4; q++) oacc[i][j][q] = 0.f;

#pragma unroll
    for (int jb = 0; jb < 4; jb++) {
        // K fragments (n = token j block of 16)
        u32 kf[4];
        {
            int r = jb * 16 + (lane & 7) + ((lane >> 4) & 1) * 8;
            ldm_x4(kf[0], kf[1], kf[2], kf[3],
                   kb + r * 48 + ((lane >> 3) & 1) * 16);
        }
        // S = Q K^T for this 64x16 block
        float s[4][2][4];
#pragma unroll
        for (int mf = 0; mf < 4; mf++)
#pragma unroll
            for (int np = 0; np < 2; np++) {
#pragma unroll
                for (int q = 0; q < 4; q++) s[mf][np][q] = 0.f;
                u32 bfrag[2] = { kf[2 * np], kf[2 * np + 1] };
                mma_fp16(s[mf][np], qa[mf], bfrag);
            }
        // decay (0.5 folded in) + pack to A fragments
        u32 aP[4][4];
#pragma unroll
        for (int mf = 0; mf < 4; mf++) {
#pragma unroll
            for (int np = 0; np < 2; np++) {
                int i0 = mf * 16 + g;
                int j0 = jb * 16 + np * 8 + t2 * 2;
                int d00 = i0 - j0;       d00 = d00 < 0 ? -d00 : d00;
                int d01 = i0 - j0 - 1;   d01 = d01 < 0 ? -d01 : d01;
                int d10 = i0 + 8 - j0;   d10 = d10 < 0 ? -d10 : d10;
                int d11 = i0 + 7 - j0;   d11 = d11 < 0 ? -d11 : d11;
                s[mf][np][0] *= decrow[d00];
                s[mf][np][1] *= decrow[d01];
                s[mf][np][2] *= decrow[d10];
                s[mf][np][3] *= decrow[d11];
            }
            __half2 h;
            h = __floats2half2_rn(s[mf][0][0], s[mf][0][1]); aP[mf][0] = *(u32*)&h;
            h = __floats2half2_rn(s[mf][0][2], s[mf][0][3]); aP[mf][1] = *(u32*)&h;
            h = __floats2half2_rn(s[mf][1][0], s[mf][1][1]); aP[mf][2] = *(u32*)&h;
            h = __floats2half2_rn(s[mf][1][2], s[mf][1][3]); aP[mf][3] = *(u32*)&h;
        }
        // V fragments via ldmatrix.trans: (n = channel, k = token)
        u32 vf[4];
        {
            int r = jb * 16 + (lane & 7) + ((lane >> 3) & 1) * 8;
            ldm_x4t(vf[0], vf[1], vf[2], vf[3],
                    vb + r * 48 + (lane >> 4) * 16);
        }
        // O += S * V
#pragma unroll
        for (int mf = 0; mf < 4; mf++)
#pragma unroll
            for (int np = 0; np < 2; np++) {
                u32 bfrag[2] = { vf[2 * np], vf[2 * np + 1] };
                mma_fp16(oacc[mf][np], aP[mf], bfrag);
            }
    }

    // write out
#pragma unroll
    for (int mf = 0; mf < 4; mf++)
#pragma unroll
        for (int np = 0; np < 2; np++) {
            int ch = n * HD_ + np * 8 + t2 * 2;
#pragma unroll
            for (int h = 0; h < 2; h++) {
                int i = mf * 16 + g + h * 8;
                size_t tok = (PASS == 0) ? ((size_t)(b * 64 + i) * 64 + fixed)
                                         : ((size_t)(b * 64 + fixed) * 64 + i);
                float v0 = oacc[mf][np][h * 2];
                float v1 = oacc[mf][np][h * 2 + 1];
                if (PASS == 0) {
                    *(float2*)(partial + tok * 128 + ch) = make_float2(v0, v1);
                } else {
                    float2 pr = *(const float2*)(partial + tok * 128 + ch);
                    *(__half2*)(out16 + tok * 128 + ch) =
                        __floats2half2_rn(pr.x + v0, pr.y + v1);
                }
            }
        }
}

// ---------------------------------------------------------------------------
extern "C" void kernel_launch(void* const* d_in, const int* in_sizes, int n_in,
                              void* d_out, int out_size) {
    const float* x      = (const float*)d_in[0];
    const float* cv1_w  = (const float*)d_in[1];
    const float* bn1_g  = (const float*)d_in[2];
    const float* bn1_b  = (const float*)d_in[3];
    const float* bn1_m  = (const float*)d_in[4];
    const float* bn1_v  = (const float*)d_in[5];
    const float* cv2_w  = (const float*)d_in[6];
    const float* bn2_g  = (const float*)d_in[7];
    const float* bn2_b  = (const float*)d_in[8];
    const float* bn2_m  = (const float*)d_in[9];
    const float* bn2_v  = (const float*)d_in[10];
    const float* ln1_g  = (const float*)d_in[11];
    const float* ln1_b  = (const float*)d_in[12];
    const float* qkv_w  = (const float*)d_in[13];
    const float* qkv_b  = (const float*)d_in[14];
    const float* proj_w = (const float*)d_in[15];
    const float* proj_b = (const float*)d_in[16];
    const float* gamma  = (const float*)d_in[17];
    const float* ln2_g  = (const float*)d_in[18];
    const float* ln2_b  = (const float*)d_in[19];
    const float* ffn_w1 = (const float*)d_in[20];
    const float* ffn_b1 = (const float*)d_in[21];
    const float* ffn_w2 = (const float*)d_in[22];
    const float* ffn_b2 = (const float*)d_in[23];
    float* out = (float*)d_out;

    __half *xt16, *cat16, *fn16, *qkv16, *attn16, *h116, *w16;
    float *y2f, *attnp, *f2;
    cudaGetSymbolAddress((void**)&xt16,   g_xt16);
    cudaGetSymbolAddress((void**)&cat16,  g_cat16);
    cudaGetSymbolAddress((void**)&y2f,    g_y2f);
    cudaGetSymbolAddress((void**)&fn16,   g_fn16);
    cudaGetSymbolAddress((void**)&qkv16,  g_qkv16);
    cudaGetSymbolAddress((void**)&attnp,  g_attnp);
    cudaGetSymbolAddress((void**)&attn16, g_attn16);
    cudaGetSymbolAddress((void**)&f2,     g_f2);
    cudaGetSymbolAddress((void**)&h116,   g_h116);
    cudaGetSymbolAddress((void**)&w16,    g_w16);

    __half* w_cv1  = w16;
    __half* w_qkv  = w_cv1 + 65536;
    __half* w_proj = w_qkv + 49152;
    __half* w_f1   = w_proj + 16384;
    __half* w_f2   = w_f1 + 32768;
    __half* w_cv2  = w_f2 + 32768;

    cudaFuncSetAttribute(gemm_fp16<EPI_CV1>,  cudaFuncAttributeMaxDynamicSharedMemorySize, GSMEM_BYTES);
    cudaFuncSetAttribute(gemm_fp16<EPI_QKV>,  cudaFuncAttributeMaxDynamicSharedMemorySize, GSMEM_BYTES);
    cudaFuncSetAttribute(gemm_fp16<EPI_PROJ>, cudaFuncAttributeMaxDynamicSharedMemorySize, GSMEM_BYTES);
    cudaFuncSetAttribute(gemm_fp16<EPI_GELU>, cudaFuncAttributeMaxDynamicSharedMemorySize, GSMEM_BYTES);
    cudaFuncSetAttribute(gemm_fp16<EPI_FFN2>, cudaFuncAttributeMaxDynamicSharedMemorySize, GSMEM_BYTES);
    cudaFuncSetAttribute(gemm_fp16<EPI_NCHW>, cudaFuncAttributeMaxDynamicSharedMemorySize, GSMEM_BYTES);

    // 0) weights -> fp16
    convert_w_kernel<<<(65536/2+255)/256, 256>>>(cv1_w,  w_cv1,  65536/2);
    convert_w_kernel<<<(49152/2+255)/256, 256>>>(qkv_w,  w_qkv,  49152/2);
    convert_w_kernel<<<(16384/2+255)/256, 256>>>(proj_w, w_proj, 16384/2);
    convert_w_kernel<<<(32768/2+255)/256, 256>>>(ffn_w1, w_f1,   32768/2);
    convert_w_kernel<<<(32768/2+255)/256, 256>>>(ffn_w2, w_f2,   32768/2);
    convert_w_kernel<<<(98304/2+255)/256, 256>>>(cv2_w,  w_cv2,  98304/2);

    // 1) x NCHW -> xt16 [token, 256]
    transpose_x_kernel<<<dim3(HW_/32, C1_/32, B_), dim3(32, 8)>>>(x, xt16);

    // 2) cv1 + BN + SiLU -> cat16[:,0:256] (+ y2 fp32)
    gemm_fp16<EPI_CV1><<<dim3(TOKENS/128, 2), 128, GSMEM_BYTES>>>(
        xt16, 256, w_cv1, 256, cat16, 384, bn1_g, bn1_b, bn1_m, bn1_v, nullptr, 0);

    // 3) LN1
    ln_kernel<<<TOKENS/8, 256>>>(y2f, 128, ln1_g, ln1_b, fn16);

    // 4) qkv
    gemm_fp16<EPI_QKV><<<dim3(TOKENS/128, 3), 128, GSMEM_BYTES>>>(
        fn16, 128, w_qkv, 128, qkv16, 384, qkv_b, nullptr, nullptr, nullptr, nullptr, 0);

    // 5) attention H then W
    attn_mma<0><<<dim3(16, NH_, B_), 128>>>(qkv16, attnp, attn16);
    attn_mma<1><<<dim3(16, NH_, B_), 128>>>(qkv16, attnp, attn16);

    // 6) proj (+ residual y2, * gamma) -> f2 fp32
    gemm_fp16<EPI_PROJ><<<dim3(TOKENS/128, 1), 128, GSMEM_BYTES>>>(
        attn16, 128, w_proj, 128, f2, 128, proj_b, gamma, nullptr, nullptr,
        y2f, 128);

    // 7) LN2
    ln_kernel<<<TOKENS/8, 256>>>(f2, 128, ln2_g, ln2_b, fn16);

    // 8) ffn1 + GELU -> h1 fp16
    gemm_fp16<EPI_GELU><<<dim3(TOKENS/128, 2), 128, GSMEM_BYTES>>>(
        fn16, 128, w_f1, 128, h116, 256, ffn_b1, nullptr, nullptr, nullptr, nullptr, 0);

    // 9) ffn2 + bias + residual f2 -> cat16[:,256:384]
    gemm_fp16<EPI_FFN2><<<dim3(TOKENS/128, 1), 128, GSMEM_BYTES>>>(
        h116, 256, w_f2, 256, cat16 + 256, 384, ffn_b2, nullptr, nullptr, nullptr,
        f2, 128);

    // 10) cv2 + BN + SiLU -> NCHW out
    gemm_fp16<EPI_NCHW><<<dim3(TOKENS/128, 2), 128, GSMEM_BYTES>>>(
        cat16, 384, w_cv2, 384, out, 0, bn2_g, bn2_b, bn2_m, bn2_v, nullptr, 0);
}

// round 5
// speedup vs baseline: 5.0138x; 1.1075x over previous
#include <cuda_runtime.h>
#include <cuda_fp16.h>
#include <math.h>

#define B_ 16
#define C1_ 256
#define C2_ 256
#define H_ 64
#define W_ 64
#define NH_ 8
#define C_ 128
#define HD_ 16
#define HW_ (H_*W_)
#define TOKENS (B_*HW_)

typedef unsigned int u32;

// -------- static scratch -----------
__device__ __half g_xt16  [(size_t)TOKENS*256];
__device__ __half g_cat16 [(size_t)TOKENS*384];
__device__ float  g_y2f   [(size_t)TOKENS*128];
__device__ __half g_fn16  [(size_t)TOKENS*128];
__device__ __half g_qkv16 [(size_t)TOKENS*384];
__device__ float  g_attnp [(size_t)TOKENS*128];
__device__ __half g_attn16[(size_t)TOKENS*128];
__device__ float  g_f2    [(size_t)TOKENS*128];
__device__ __half g_h116  [(size_t)TOKENS*256];
__device__ __half g_w16[65536+49152+16384+32768+32768+98304];

// ---------------------------------------------------------------------------
__device__ __forceinline__ u32 smem_u32(const void* p) {
    u32 a;
    asm("{ .reg .u64 t; cvta.to.shared.u64 t, %1; cvt.u32.u64 %0, t; }"
        : "=r"(a) : "l"(p));
    return a;
}
__device__ __forceinline__ void mma_fp16(float* c, const u32* a, const u32* b) {
    asm volatile(
        "mma.sync.aligned.m16n8k16.row.col.f32.f16.f16.f32 "
        "{%0,%1,%2,%3}, {%4,%5,%6,%7}, {%8,%9}, {%0,%1,%2,%3};"
        : "+f"(c[0]), "+f"(c[1]), "+f"(c[2]), "+f"(c[3])
        : "r"(a[0]), "r"(a[1]), "r"(a[2]), "r"(a[3]), "r"(b[0]), "r"(b[1]));
}
__device__ __forceinline__ void ldm_x4(u32& r0, u32& r1, u32& r2, u32& r3, u32 a) {
    asm volatile("ldmatrix.sync.aligned.m8n8.x4.shared.b16 {%0,%1,%2,%3}, [%4];"
        : "=r"(r0), "=r"(r1), "=r"(r2), "=r"(r3) : "r"(a));
}
__device__ __forceinline__ void ldm_x4t(u32& r0, u32& r1, u32& r2, u32& r3, u32 a) {
    asm volatile("ldmatrix.sync.aligned.m8n8.x4.trans.shared.b16 {%0,%1,%2,%3}, [%4];"
        : "=r"(r0), "=r"(r1), "=r"(r2), "=r"(r3) : "r"(a));
}
__device__ __forceinline__ void cp16(u32 dst, const void* src) {
    asm volatile("cp.async.cg.shared.global [%0], [%1], 16;" :: "r"(dst), "l"(src));
}

// ---------------------------------------------------------------------------
// All six weight tensors fp32 -> fp16 in one launch. blockIdx.y = tensor id.
// ---------------------------------------------------------------------------
__global__ void convert_w_all(const float* __restrict__ s0, const float* __restrict__ s1,
                              const float* __restrict__ s2, const float* __restrict__ s3,
                              const float* __restrict__ s4, const float* __restrict__ s5,
                              __half* __restrict__ dst) {
    const int sizes[6] = {65536, 49152, 16384, 32768, 32768, 98304};
    const int offs [6] = {0, 65536, 114688, 131072, 163840, 196608};
    int t = blockIdx.y;
    const float* src = t == 0 ? s0 : t == 1 ? s1 : t == 2 ? s2 :
                       t == 3 ? s3 : t == 4 ? s4 : s5;
    int n2 = sizes[t] >> 1;
    int i = blockIdx.x * 256 + threadIdx.x;
    if (i < n2) {
        float2 v = *(const float2*)(src + 2 * i);
        *(__half2*)(dst + offs[t] + 2 * i) = __floats2half2_rn(v.x, v.y);
    }
}

// NCHW -> [token, channel] fp16 transpose
__global__ void transpose_x_kernel(const float* __restrict__ x,
                                   __half* __restrict__ xt) {
    __shared__ float tile[32][33];
    int b  = blockIdx.z;
    int p0 = blockIdx.x * 32;
    int c0 = blockIdx.y * 32;
    const float* xb = x + (size_t)b * C1_ * HW_;
    __half*     xtb = xt + (size_t)b * HW_ * C1_;
#pragma unroll
    for (int i = 0; i < 32; i += 8)
        tile[threadIdx.y + i][threadIdx.x] =
            xb[(size_t)(c0 + threadIdx.y + i) * HW_ + p0 + threadIdx.x];
    __syncthreads();
#pragma unroll
    for (int i = 0; i < 32; i += 8)
        xtb[(size_t)(p0 + threadIdx.y + i) * C1_ + c0 + threadIdx.x] =
            __float2half_rn(tile[threadIdx.x][threadIdx.y + i]);
}

// ---------------------------------------------------------------------------
// fp16 GEMM: C[M,N] = A[M,K] @ Wt[N,K]^T. CTA 128x128, 256 thr (8 warps 2x4,
// warp tile 64x32). BK=64, double-buffered cp.async, ldmatrix. rows 144B.
// Optional fused LayerNorm over the 128-col tile (full rows).
// ---------------------------------------------------------------------------
enum { EPI_CV1 = 0, EPI_QKV = 1, EPI_PROJ = 2, EPI_GELU = 3,
       EPI_FFN2 = 4, EPI_NCHW = 5 };

#define STG_BYTES 36864
#define GSMEM_BYTES (2*STG_BYTES)    // 73728 (also covers 128x129 fp32 staging)

template <int EPI, bool LN>
__global__ void __launch_bounds__(256)
gemm_fp16(const __half* __restrict__ A, int lda,
          const __half* __restrict__ Wt, int K,
          void* __restrict__ Cpv, int ldc,
          const float* __restrict__ p0, const float* __restrict__ p1,
          const float* __restrict__ p2, const float* __restrict__ p3,
          const float* __restrict__ Rs, int ldr,
          const float* __restrict__ lng, const float* __restrict__ lnb,
          __half* __restrict__ fnout) {
    extern __shared__ __align__(16) char smem[];
    const u32 sb = smem_u32(smem);
    const int tid = threadIdx.x, wid = tid >> 5, lane = tid & 31;
    const int wm = (wid >> 2) * 64, wn = (wid & 3) * 32;
    const int g = lane >> 2, t2 = lane & 3;
    const int row0 = blockIdx.x * 128, col0 = blockIdx.y * 128;
    const int lrow = tid >> 3, lc8 = tid & 7;    // lrow 0..31

    float acc[4][4][4];
#pragma unroll
    for (int i = 0; i < 4; i++)
#pragma unroll
        for (int j = 0; j < 4; j++)
#pragma unroll
            for (int q = 0; q < 4; q++) acc[i][j][q] = 0.f;

    const int nch = K >> 6;
    auto issue = [&](int c) {
        u32 ab = sb + (c & 1) * STG_BYTES;
        u32 bb = ab + 18432;
        const __half* Ag = A  + (size_t)row0 * lda + c * 64;
        const __half* Bg = Wt + (size_t)col0 * K   + c * 64;
#pragma unroll
        for (int i = 0; i < 4; i++) {
            int r = i * 32 + lrow;
            cp16(ab + r * 144 + lc8 * 16, Ag + (size_t)r * lda + lc8 * 8);
            cp16(bb + r * 144 + lc8 * 16, Bg + (size_t)r * K   + lc8 * 8);
        }
    };

    issue(0);
    asm volatile("cp.async.commit_group;");
    for (int c = 0; c < nch; c++) {
        if (c + 1 < nch) {
            issue(c + 1);
            asm volatile("cp.async.commit_group;");
            asm volatile("cp.async.wait_group 1;");
        } else {
            asm volatile("cp.async.wait_group 0;");
        }
        __syncthreads();
        u32 ab = sb + (c & 1) * STG_BYTES;
        u32 bb = ab + 18432;
#pragma unroll
        for (int kb = 0; kb < 4; kb++) {
            u32 a[4][4], b[4][2];
#pragma unroll
            for (int mf = 0; mf < 4; mf++) {
                int r = wm + mf * 16 + (lane & 7) + ((lane >> 3) & 1) * 8;
                ldm_x4(a[mf][0], a[mf][1], a[mf][2], a[mf][3],
                       ab + r * 144 + kb * 32 + (lane >> 4) * 16);
            }
#pragma unroll
            for (int np = 0; np < 2; np++) {
                int r = wn + np * 16 + (lane & 7) + ((lane >> 4) & 1) * 8;
                ldm_x4(b[2*np][0], b[2*np][1], b[2*np+1][0], b[2*np+1][1],
                       bb + r * 144 + kb * 32 + ((lane >> 3) & 1) * 16);
            }
#pragma unroll
            for (int mf = 0; mf < 4; mf++)
#pragma unroll
                for (int nf = 0; nf < 4; nf++)
                    mma_fp16(acc[mf][nf], a[mf], b[nf]);
        }
        __syncthreads();
    }

    float* stg = (float*)smem;   // 128x129 fp32 staging (fits in 73728B)
    const bool doLN = LN && (EPI != EPI_CV1 || blockIdx.y == 1);

    // ------------- epilogue -------------
    if constexpr (EPI == EPI_NCHW) {
#pragma unroll
        for (int mf = 0; mf < 4; mf++)
#pragma unroll
            for (int nf = 0; nf < 4; nf++) {
                int r = wm + mf * 16 + g;
                int cl = wn + nf * 8 + t2 * 2;
                stg[r * 129 + cl]           = acc[mf][nf][0];
                stg[r * 129 + cl + 1]       = acc[mf][nf][1];
                stg[(r + 8) * 129 + cl]     = acc[mf][nf][2];
                stg[(r + 8) * 129 + cl + 1] = acc[mf][nf][3];
            }
        __syncthreads();
        float* Cp = (float*)Cpv;
        for (int it = 0; it < 64; it++) {
            int idx  = it * 256 + tid;
            int lcol = idx >> 7;
            int r    = idx & 127;
            int col  = col0 + lcol;
            int row  = row0 + r;
            float v  = stg[r * 129 + lcol];
            float sc = p0[col] * rsqrtf(p3[col] + 1e-5f);
            v = v * sc + (p1[col] - p2[col] * sc);
            v = v / (1.f + expf(-v));
            Cp[(((size_t)(row >> 12)) * C2_ + col) * 4096 + (row & 4095)] = v;
        }
    } else {
#pragma unroll
        for (int mf = 0; mf < 4; mf++) {
#pragma unroll
            for (int nf = 0; nf < 4; nf++) {
                int lcol = wn + nf * 8 + t2 * 2;
                int col  = col0 + lcol;
                float e0 = 0.f, e1 = 0.f, f0 = 0.f, f1 = 0.f;
                if constexpr (EPI == EPI_CV1) {
                    e0 = p0[col]     * rsqrtf(p3[col]     + 1e-5f);
                    e1 = p0[col + 1] * rsqrtf(p3[col + 1] + 1e-5f);
                    f0 = p1[col]     - p2[col]     * e0;
                    f1 = p1[col + 1] - p2[col + 1] * e1;
                } else if constexpr (EPI == EPI_PROJ) {
                    e0 = p0[col]; e1 = p0[col + 1];
                    f0 = p1[col]; f1 = p1[col + 1];
                } else {
                    e0 = p0[col]; e1 = p0[col + 1];
                }
#pragma unroll
                for (int h = 0; h < 2; h++) {
                    int r   = wm + mf * 16 + g + h * 8;
                    int row = row0 + r;
                    float v0 = acc[mf][nf][h * 2];
                    float v1 = acc[mf][nf][h * 2 + 1];
                    if constexpr (EPI == EPI_CV1) {
                        v0 = v0 * e0 + f0; v0 = v0 / (1.f + expf(-v0));
                        v1 = v1 * e1 + f1; v1 = v1 / (1.f + expf(-v1));
                        *(__half2*)((__half*)Cpv + (size_t)row * 384 + col) =
                            __floats2half2_rn(v0, v1);
                        if (col0 == 128)
                            *(float2*)(g_y2f + (size_t)row * 128 + lcol) =
                                make_float2(v0, v1);
                    } else if constexpr (EPI == EPI_QKV) {
                        v0 += e0; v1 += e1;
                        *(__half2*)((__half*)Cpv + (size_t)row * ldc + col) =
                            __floats2half2_rn(v0, v1);
                    } else if constexpr (EPI == EPI_PROJ) {
                        float2 rs = *(const float2*)(Rs + (size_t)row * ldr + col);
                        v0 = rs.x + (v0 + e0) * f0;
                        v1 = rs.y + (v1 + e1) * f1;
                        *(float2*)((float*)Cpv + (size_t)row * ldc + col) =
                            make_float2(v0, v1);
                    } else if constexpr (EPI == EPI_GELU) {
                        v0 += e0; v1 += e1;
                        v0 = 0.5f * v0 * (1.f + erff(v0 * 0.70710678118654752f));
                        v1 = 0.5f * v1 * (1.f + erff(v1 * 0.70710678118654752f));
                        *(__half2*)((__half*)Cpv + (size_t)row * ldc + col) =
                            __floats2half2_rn(v0, v1);
                    } else if constexpr (EPI == EPI_FFN2) {
                        float2 rs = *(const float2*)(Rs + (size_t)row * ldr + col);
                        v0 = v0 + e0 + rs.x;
                        v1 = v1 + e1 + rs.y;
                        *(__half2*)((__half*)Cpv + (size_t)row * ldc + col) =
                            __floats2half2_rn(v0, v1);
                    }
                    if (doLN) {
                        stg[r * 129 + lcol]     = v0;
                        stg[r * 129 + lcol + 1] = v1;
                    }
                }
            }
        }
        if (doLN) {
            __syncthreads();
            // 8 warps x 16 rows each; LN over 128 cols
#pragma unroll
            for (int rr = 0; rr < 16; rr++) {
                int r = wid * 16 + rr;
                float v[4];
                float s = 0.f;
#pragma unroll
                for (int i = 0; i < 4; i++) {
                    v[i] = stg[r * 129 + lane + 32 * i];
                    s += v[i];
                }
#pragma unroll
                for (int o = 16; o; o >>= 1) s += __shfl_xor_sync(~0u, s, o);
                float mu = s * (1.f / 128.f);
                float q = 0.f;
#pragma unroll
                for (int i = 0; i < 4; i++) { float d = v[i] - mu; q += d * d; }
#pragma unroll
                for (int o = 16; o; o >>= 1) q += __shfl_xor_sync(~0u, q, o);
                float rsd = rsqrtf(q * (1.f / 128.f) + 1e-5f);
#pragma unroll
                for (int i = 0; i < 4; i++) {
                    int cc = lane + 32 * i;
                    fnout[(size_t)(row0 + r) * 128 + cc] =
                        __float2half_rn((v[i] - mu) * rsd * lng[cc] + lnb[cc]);
                }
            }
        }
    }
}

// ---------------------------------------------------------------------------
// Tensor-core retention attention. One warp per (b, head, fixed line).
// ---------------------------------------------------------------------------
template <int PASS>
__global__ void __launch_bounds__(128)
attn_mma(const __half* __restrict__ qkv,
         float* __restrict__ partial,
         __half* __restrict__ out16) {
    __shared__ __half sQ[4][64 * 24];
    __shared__ __half sK[4][64 * 24];
    __shared__ __half sV[4][64 * 24];
    __shared__ float decrow[64];

    const int tid = threadIdx.x, wid = tid >> 5, lane = tid & 31;
    const int g = lane >> 2, t2 = lane & 3;
    const int fixed = blockIdx.x * 4 + wid;
    const int n = blockIdx.y, b = blockIdx.z;

    if (tid < 64) {
        float dec = logf(1.f - exp2f(-2.f - 0.5f * (float)n));
        decrow[tid] = 0.5f * expf(dec * (float)tid);
    }

#pragma unroll
    for (int tt = 0; tt < 2; tt++) {
        int t = lane + tt * 32;
        size_t tok = (PASS == 0) ? ((size_t)(b * 64 + t) * 64 + fixed)
                                 : ((size_t)(b * 64 + fixed) * 64 + t);
        const uint4* src = (const uint4*)(qkv + tok * 384 + n * HD_);
        *(uint4*)&sQ[wid][t * 24]     = src[0];
        *(uint4*)&sQ[wid][t * 24 + 8] = src[1];
        *(uint4*)&sK[wid][t * 24]     = src[16];
        *(uint4*)&sK[wid][t * 24 + 8] = src[17];
        *(uint4*)&sV[wid][t * 24]     = src[32];
        *(uint4*)&sV[wid][t * 24 + 8] = src[33];
    }
    __syncthreads();

    const u32 qb = smem_u32(&sQ[wid][0]);
    const u32 kb = smem_u32(&sK[wid][0]);
    const u32 vb = smem_u32(&sV[wid][0]);

    u32 qa[4][4];
#pragma unroll
    for (int mf = 0; mf < 4; mf++) {
        int r = mf * 16 + (lane & 7) + ((lane >> 3) & 1) * 8;
        ldm_x4(qa[mf][0], qa[mf][1], qa[mf][2], qa[mf][3],
               qb + r * 48 + (lane >> 4) * 16);
    }

    float oacc[4][2][4];
#pragma unroll
    for (int i = 0; i < 4; i++)
#pragma unroll
        for (int j = 0; j < 2; j++)
#pragma unroll
            for (int q = 0; q < 4; q++) oacc[i][j][q] = 0.f;

#pragma unroll
    for (int jb = 0; jb < 4; jb++) {
        u32 kf[4];
        {
            int r = jb * 16 + (lane & 7) + ((lane >> 4) & 1) * 8;
            ldm_x4(kf[0], kf[1], kf[2], kf[3],
                   kb + r * 48 + ((lane >> 3) & 1) * 16);
        }
        float s[4][2][4];
#pragma unroll
        for (int mf = 0; mf < 4; mf++)
#pragma unroll
            for (int np = 0; np < 2; np++) {
#pragma unroll
                for (int q = 0; q < 4; q++) s[mf][np][q] = 0.f;
                u32 bfrag[2] = { kf[2 * np], kf[2 * np + 1] };
                mma_fp16(s[mf][np], qa[mf], bfrag);
            }
        u32 aP[4][4];
#pragma unroll
        for (int mf = 0; mf < 4; mf++) {
#pragma unroll
            for (int np = 0; np < 2; np++) {
                int i0 = mf * 16 + g;
                int j0 = jb * 16 + np * 8 + t2 * 2;
                int d00 = i0 - j0;       d00 = d00 < 0 ? -d00 : d00;
                int d01 = i0 - j0 - 1;   d01 = d01 < 0 ? -d01 : d01;
                int d10 = i0 + 8 - j0;   d10 = d10 < 0 ? -d10 : d10;
                int d11 = i0 + 7 - j0;   d11 = d11 < 0 ? -d11 : d11;
                s[mf][np][0] *= decrow[d00];
                s[mf][np][1] *= decrow[d01];
                s[mf][np][2] *= decrow[d10];
                s[mf][np][3] *= decrow[d11];
            }
            __half2 h;
            h = __floats2half2_rn(s[mf][0][0], s[mf][0][1]); aP[mf][0] = *(u32*)&h;
            h = __floats2half2_rn(s[mf][0][2], s[mf][0][3]); aP[mf][1] = *(u32*)&h;
            h = __floats2half2_rn(s[mf][1][0], s[mf][1][1]); aP[mf][2] = *(u32*)&h;
            h = __floats2half2_rn(s[mf][1][2], s[mf][1][3]); aP[mf][3] = *(u32*)&h;
        }
        u32 vf[4];
        {
            int r = jb * 16 + (lane & 7) + ((lane >> 3) & 1) * 8;
            ldm_x4t(vf[0], vf[1], vf[2], vf[3],
                    vb + r * 48 + (lane >> 4) * 16);
        }
#pragma unroll
        for (int mf = 0; mf < 4; mf++)
#pragma unroll
            for (int np = 0; np < 2; np++) {
                u32 bfrag[2] = { vf[2 * np], vf[2 * np + 1] };
                mma_fp16(oacc[mf][np], aP[mf], bfrag);
            }
    }

#pragma unroll
    for (int mf = 0; mf < 4; mf++)
#pragma unroll
        for (int np = 0; np < 2; np++) {
            int ch = n * HD_ + np * 8 + t2 * 2;
#pragma unroll
            for (int h = 0; h < 2; h++) {
                int i = mf * 16 + g + h * 8;
                size_t tok = (PASS == 0) ? ((size_t)(b * 64 + i) * 64 + fixed)
                                         : ((size_t)(b * 64 + fixed) * 64 + i);
                float v0 = oacc[mf][np][h * 2];
                float v1 = oacc[mf][np][h * 2 + 1];
                if (PASS == 0) {
                    *(float2*)(partial + tok * 128 + ch) = make_float2(v0, v1);
                } else {
                    float2 pr = *(const float2*)(partial + tok * 128 + ch);
                    *(__half2*)(out16 + tok * 128 + ch) =
                        __floats2half2_rn(pr.x + v0, pr.y + v1);
                }
            }
        }
}

// ---------------------------------------------------------------------------
extern "C" void kernel_launch(void* const* d_in, const int* in_sizes, int n_in,
                              void* d_out, int out_size) {
    const float* x      = (const float*)d_in[0];
    const float* cv1_w  = (const float*)d_in[1];
    const float* bn1_g  = (const float*)d_in[2];
    const float* bn1_b  = (const float*)d_in[3];
    const float* bn1_m  = (const float*)d_in[4];
    const float* bn1_v  = (const float*)d_in[5];
    const float* cv2_w  = (const float*)d_in[6];
    const float* bn2_g  = (const float*)d_in[7];
    const float* bn2_b  = (const float*)d_in[8];
    const float* bn2_m  = (const float*)d_in[9];
    const float* bn2_v  = (const float*)d_in[10];
    const float* ln1_g  = (const float*)d_in[11];
    const float* ln1_b  = (const float*)d_in[12];
    const float* qkv_w  = (const float*)d_in[13];
    const float* qkv_b  = (const float*)d_in[14];
    const float* proj_w = (const float*)d_in[15];
    const float* proj_b = (const float*)d_in[16];
    const float* gamma  = (const float*)d_in[17];
    const float* ln2_g  = (const float*)d_in[18];
    const float* ln2_b  = (const float*)d_in[19];
    const float* ffn_w1 = (const float*)d_in[20];
    const float* ffn_b1 = (const float*)d_in[21];
    const float* ffn_w2 = (const float*)d_in[22];
    const float* ffn_b2 = (const float*)d_in[23];
    float* out = (float*)d_out;

    __half *xt16, *cat16, *fn16, *qkv16, *attn16, *h116, *w16;
    float *y2f, *attnp, *f2;
    cudaGetSymbolAddress((void**)&xt16,   g_xt16);
    cudaGetSymbolAddress((void**)&cat16,  g_cat16);
    cudaGetSymbolAddress((void**)&y2f,    g_y2f);
    cudaGetSymbolAddress((void**)&fn16,   g_fn16);
    cudaGetSymbolAddress((void**)&qkv16,  g_qkv16);
    cudaGetSymbolAddress((void**)&attnp,  g_attnp);
    cudaGetSymbolAddress((void**)&attn16, g_attn16);
    cudaGetSymbolAddress((void**)&f2,     g_f2);
    cudaGetSymbolAddress((void**)&h116,   g_h116);
    cudaGetSymbolAddress((void**)&w16,    g_w16);

    __half* w_cv1  = w16;
    __half* w_qkv  = w_cv1 + 65536;
    __half* w_proj = w_qkv + 49152;
    __half* w_f1   = w_proj + 16384;
    __half* w_f2   = w_f1 + 32768;
    __half* w_cv2  = w_f2 + 32768;

    cudaFuncSetAttribute(gemm_fp16<EPI_CV1,  true >, cudaFuncAttributeMaxDynamicSharedMemorySize, GSMEM_BYTES);
    cudaFuncSetAttribute(gemm_fp16<EPI_QKV,  false>, cudaFuncAttributeMaxDynamicSharedMemorySize, GSMEM_BYTES);
    cudaFuncSetAttribute(gemm_fp16<EPI_PROJ, true >, cudaFuncAttributeMaxDynamicSharedMemorySize, GSMEM_BYTES);
    cudaFuncSetAttribute(gemm_fp16<EPI_GELU, false>, cudaFuncAttributeMaxDynamicSharedMemorySize, GSMEM_BYTES);
    cudaFuncSetAttribute(gemm_fp16<EPI_FFN2, false>, cudaFuncAttributeMaxDynamicSharedMemorySize, GSMEM_BYTES);
    cudaFuncSetAttribute(gemm_fp16<EPI_NCHW, false>, cudaFuncAttributeMaxDynamicSharedMemorySize, GSMEM_BYTES);

    // 0) weights -> fp16 (single launch)
    convert_w_all<<<dim3(192, 6), 256>>>(cv1_w, qkv_w, proj_w, ffn_w1, ffn_w2,
                                         cv2_w, w16);

    // 1) x NCHW -> xt16
    transpose_x_kernel<<<dim3(HW_/32, C1_/32, B_), dim3(32, 8)>>>(x, xt16);

    // 2) cv1 + BN + SiLU -> cat16[:,0:256] (+ y2f, + fused LN1 -> fn16)
    gemm_fp16<EPI_CV1, true><<<dim3(TOKENS/128, 2), 256, GSMEM_BYTES>>>(
        xt16, 256, w_cv1, 256, cat16, 384, bn1_g, bn1_b, bn1_m, bn1_v,
        nullptr, 0, ln1_g, ln1_b, fn16);

    // 3) qkv
    gemm_fp16<EPI_QKV, false><<<dim3(TOKENS/128, 3), 256, GSMEM_BYTES>>>(
        fn16, 128, w_qkv, 128, qkv16, 384, qkv_b, nullptr, nullptr, nullptr,
        nullptr, 0, nullptr, nullptr, nullptr);

    // 4) attention H then W
    attn_mma<0><<<dim3(16, NH_, B_), 128>>>(qkv16, attnp, attn16);
    attn_mma<1><<<dim3(16, NH_, B_), 128>>>(qkv16, attnp, attn16);

    // 5) proj (+res y2, *gamma) -> f2 (+ fused LN2 -> fn16)
    gemm_fp16<EPI_PROJ, true><<<dim3(TOKENS/128, 1), 256, GSMEM_BYTES>>>(
        attn16, 128, w_proj, 128, f2, 128, proj_b, gamma, nullptr, nullptr,
        y2f, 128, ln2_g, ln2_b, fn16);

    // 6) ffn1 + GELU
    gemm_fp16<EPI_GELU, false><<<dim3(TOKENS/128, 2), 256, GSMEM_BYTES>>>(
        fn16, 128, w_f1, 128, h116, 256, ffn_b1, nullptr, nullptr, nullptr,
        nullptr, 0, nullptr, nullptr, nullptr);

    // 7) ffn2 + bias + res f2 -> cat16[:,256:384]
    gemm_fp16<EPI_FFN2, false><<<dim3(TOKENS/128, 1), 256, GSMEM_BYTES>>>(
        h116, 256, w_f2, 256, cat16 + 256, 384, ffn_b2, nullptr, nullptr, nullptr,
        f2, 128, nullptr, nullptr, nullptr);

    // 8) cv2 + BN + SiLU -> NCHW out
    gemm_fp16<EPI_NCHW, false><<<dim3(TOKENS/128, 2), 256, GSMEM_BYTES>>>(
        cat16, 384, w_cv2, 384, out, 0, bn2_g, bn2_b, bn2_m, bn2_v,
        nullptr, 0, nullptr, nullptr, nullptr);
}

// round 6
// speedup vs baseline: 5.2197x; 1.0411x over previous
#include <cuda_runtime.h>
#include <cuda_fp16.h>
#include <math.h>

#define B_ 16
#define C1_ 256
#define C2_ 256
#define H_ 64
#define W_ 64
#define NH_ 8
#define C_ 128
#define HD_ 16
#define HW_ (H_*W_)
#define TOKENS (B_*HW_)

typedef unsigned int u32;

// -------- static scratch -----------
__device__ __half g_xt16  [(size_t)TOKENS*256];
__device__ __half g_cat16 [(size_t)TOKENS*384];
__device__ float  g_y2f   [(size_t)TOKENS*128];
__device__ __half g_fn16  [(size_t)TOKENS*128];
__device__ __half g_qkv16 [(size_t)TOKENS*384];
__device__ float  g_attnp [(size_t)TOKENS*128];
__device__ __half g_attn16[(size_t)TOKENS*128];
__device__ float  g_f2    [(size_t)TOKENS*128];
__device__ __half g_h116  [(size_t)TOKENS*256];
__device__ __half g_w16[65536+49152+16384+32768+32768+98304];

// ---------------------------------------------------------------------------
__device__ __forceinline__ u32 smem_u32(const void* p) {
    u32 a;
    asm("{ .reg .u64 t; cvta.to.shared.u64 t, %1; cvt.u32.u64 %0, t; }"
        : "=r"(a) : "l"(p));
    return a;
}
__device__ __forceinline__ void mma_fp16(float* c, const u32* a, const u32* b) {
    asm volatile(
        "mma.sync.aligned.m16n8k16.row.col.f32.f16.f16.f32 "
        "{%0,%1,%2,%3}, {%4,%5,%6,%7}, {%8,%9}, {%0,%1,%2,%3};"
        : "+f"(c[0]), "+f"(c[1]), "+f"(c[2]), "+f"(c[3])
        : "r"(a[0]), "r"(a[1]), "r"(a[2]), "r"(a[3]), "r"(b[0]), "r"(b[1]));
}
__device__ __forceinline__ void ldm_x4(u32& r0, u32& r1, u32& r2, u32& r3, u32 a) {
    asm volatile("ldmatrix.sync.aligned.m8n8.x4.shared.b16 {%0,%1,%2,%3}, [%4];"
        : "=r"(r0), "=r"(r1), "=r"(r2), "=r"(r3) : "r"(a));
}
__device__ __forceinline__ void ldm_x4t(u32& r0, u32& r1, u32& r2, u32& r3, u32 a) {
    asm volatile("ldmatrix.sync.aligned.m8n8.x4.trans.shared.b16 {%0,%1,%2,%3}, [%4];"
        : "=r"(r0), "=r"(r1), "=r"(r2), "=r"(r3) : "r"(a));
}
__device__ __forceinline__ void cp16(u32 dst, const void* src) {
    asm volatile("cp.async.cg.shared.global [%0], [%1], 16;" :: "r"(dst), "l"(src));
}

// ---------------------------------------------------------------------------
__global__ void convert_w_all(const float* __restrict__ s0, const float* __restrict__ s1,
                              const float* __restrict__ s2, const float* __restrict__ s3,
                              const float* __restrict__ s4, const float* __restrict__ s5,
                              __half* __restrict__ dst) {
    const int sizes[6] = {65536, 49152, 16384, 32768, 32768, 98304};
    const int offs [6] = {0, 65536, 114688, 131072, 163840, 196608};
    int t = blockIdx.y;
    const float* src = t == 0 ? s0 : t == 1 ? s1 : t == 2 ? s2 :
                       t == 3 ? s3 : t == 4 ? s4 : s5;
    int n2 = sizes[t] >> 1;
    int i = blockIdx.x * 256 + threadIdx.x;
    if (i < n2) {
        float2 v = *(const float2*)(src + 2 * i);
        *(__half2*)(dst + offs[t] + 2 * i) = __floats2half2_rn(v.x, v.y);
    }
}

__global__ void transpose_x_kernel(const float* __restrict__ x,
                                   __half* __restrict__ xt) {
    __shared__ float tile[32][33];
    int b  = blockIdx.z;
    int p0 = blockIdx.x * 32;
    int c0 = blockIdx.y * 32;
    const float* xb = x + (size_t)b * C1_ * HW_;
    __half*     xtb = xt + (size_t)b * HW_ * C1_;
#pragma unroll
    for (int i = 0; i < 32; i += 8)
        tile[threadIdx.y + i][threadIdx.x] =
            xb[(size_t)(c0 + threadIdx.y + i) * HW_ + p0 + threadIdx.x];
    __syncthreads();
#pragma unroll
    for (int i = 0; i < 32; i += 8)
        xtb[(size_t)(p0 + threadIdx.y + i) * C1_ + c0 + threadIdx.x] =
            __float2half_rn(tile[threadIdx.x][threadIdx.y + i]);
}

enum { EPI_CV1 = 0, EPI_QKV = 1, EPI_PROJ = 2, EPI_GELU = 3,
       EPI_FFN2 = 4, EPI_NCHW = 5 };

// ---------------------------------------------------------------------------
// gemm128: CTA 128x128, 8 warps (2m x 4n, warp 64x32). For LN-fused GEMMs.
// ---------------------------------------------------------------------------
#define STG128 36864
#define SM128_BYTES (2*STG128)

template <int EPI>
__global__ void __launch_bounds__(256)
gemm128(const __half* __restrict__ A, int lda,
        const __half* __restrict__ Wt, int K,
        void* __restrict__ Cpv, int ldc,
        const float* __restrict__ p0, const float* __restrict__ p1,
        const float* __restrict__ p2, const float* __restrict__ p3,
        const float* __restrict__ Rs, int ldr,
        const float* __restrict__ lng, const float* __restrict__ lnb,
        __half* __restrict__ fnout) {
    extern __shared__ __align__(16) char smem[];
    const u32 sb = smem_u32(smem);
    const int tid = threadIdx.x, wid = tid >> 5, lane = tid & 31;
    const int wm = (wid >> 2) * 64, wn = (wid & 3) * 32;
    const int g = lane >> 2, t2 = lane & 3;
    const int row0 = blockIdx.x * 128, col0 = blockIdx.y * 128;
    const int lrow = tid >> 3, lc8 = tid & 7;

    float acc[4][4][4];
#pragma unroll
    for (int i = 0; i < 4; i++)
#pragma unroll
        for (int j = 0; j < 4; j++)
#pragma unroll
            for (int q = 0; q < 4; q++) acc[i][j][q] = 0.f;

    const int nch = K >> 6;
    auto issue = [&](int c) {
        u32 ab = sb + (c & 1) * STG128;
        u32 bb = ab + 18432;
        const __half* Ag = A  + (size_t)row0 * lda + c * 64;
        const __half* Bg = Wt + (size_t)col0 * K   + c * 64;
#pragma unroll
        for (int i = 0; i < 4; i++) {
            int r = i * 32 + lrow;
            cp16(ab + r * 144 + lc8 * 16, Ag + (size_t)r * lda + lc8 * 8);
            cp16(bb + r * 144 + lc8 * 16, Bg + (size_t)r * K   + lc8 * 8);
        }
    };

    issue(0);
    asm volatile("cp.async.commit_group;");
    for (int c = 0; c < nch; c++) {
        if (c + 1 < nch) {
            issue(c + 1);
            asm volatile("cp.async.commit_group;");
            asm volatile("cp.async.wait_group 1;");
        } else {
            asm volatile("cp.async.wait_group 0;");
        }
        __syncthreads();
        u32 ab = sb + (c & 1) * STG128;
        u32 bb = ab + 18432;
#pragma unroll
        for (int kb = 0; kb < 4; kb++) {
            u32 a[4][4], b[4][2];
#pragma unroll
            for (int mf = 0; mf < 4; mf++) {
                int r = wm + mf * 16 + (lane & 7) + ((lane >> 3) & 1) * 8;
                ldm_x4(a[mf][0], a[mf][1], a[mf][2], a[mf][3],
                       ab + r * 144 + kb * 32 + (lane >> 4) * 16);
            }
#pragma unroll
            for (int np = 0; np < 2; np++) {
                int r = wn + np * 16 + (lane & 7) + ((lane >> 4) & 1) * 8;
                ldm_x4(b[2*np][0], b[2*np][1], b[2*np+1][0], b[2*np+1][1],
                       bb + r * 144 + kb * 32 + ((lane >> 3) & 1) * 16);
            }
#pragma unroll
            for (int mf = 0; mf < 4; mf++)
#pragma unroll
                for (int nf = 0; nf < 4; nf++)
                    mma_fp16(acc[mf][nf], a[mf], b[nf]);
        }
        __syncthreads();
    }

    float* stg = (float*)smem;   // 128x129 staging fits in 73728
    const bool doLN = (EPI != EPI_CV1) || (blockIdx.y == 1);

#pragma unroll
    for (int mf = 0; mf < 4; mf++) {
#pragma unroll
        for (int nf = 0; nf < 4; nf++) {
            int lcol = wn + nf * 8 + t2 * 2;
            int col  = col0 + lcol;
            float e0 = 0.f, e1 = 0.f, f0 = 0.f, f1 = 0.f;
            if constexpr (EPI == EPI_CV1) {
                e0 = p0[col]     * rsqrtf(p3[col]     + 1e-5f);
                e1 = p0[col + 1] * rsqrtf(p3[col + 1] + 1e-5f);
                f0 = p1[col]     - p2[col]     * e0;
                f1 = p1[col + 1] - p2[col + 1] * e1;
            } else if constexpr (EPI == EPI_PROJ) {
                e0 = p0[col]; e1 = p0[col + 1];
                f0 = p1[col]; f1 = p1[col + 1];
            }
#pragma unroll
            for (int h = 0; h < 2; h++) {
                int r   = wm + mf * 16 + g + h * 8;
                int row = row0 + r;
                float v0 = acc[mf][nf][h * 2];
                float v1 = acc[mf][nf][h * 2 + 1];
                if constexpr (EPI == EPI_CV1) {
                    v0 = v0 * e0 + f0; v0 = v0 / (1.f + __expf(-v0));
                    v1 = v1 * e1 + f1; v1 = v1 / (1.f + __expf(-v1));
                    *(__half2*)((__half*)Cpv + (size_t)row * 384 + col) =
                        __floats2half2_rn(v0, v1);
                    if (col0 == 128)
                        *(float2*)(g_y2f + (size_t)row * 128 + lcol) =
                            make_float2(v0, v1);
                } else if constexpr (EPI == EPI_PROJ) {
                    float2 rs = *(const float2*)(Rs + (size_t)row * ldr + col);
                    v0 = rs.x + (v0 + e0) * f0;
                    v1 = rs.y + (v1 + e1) * f1;
                    *(float2*)((float*)Cpv + (size_t)row * ldc + col) =
                        make_float2(v0, v1);
                }
                if (doLN) {
                    stg[r * 129 + lcol]     = v0;
                    stg[r * 129 + lcol + 1] = v1;
                }
            }
        }
    }
    if (doLN) {
        __syncthreads();
#pragma unroll
        for (int rr = 0; rr < 16; rr++) {
            int r = wid * 16 + rr;
            float v[4];
            float s = 0.f;
#pragma unroll
            for (int i = 0; i < 4; i++) {
                v[i] = stg[r * 129 + lane + 32 * i];
                s += v[i];
            }
#pragma unroll
            for (int o = 16; o; o >>= 1) s += __shfl_xor_sync(~0u, s, o);
            float mu = s * (1.f / 128.f);
            float q = 0.f;
#pragma unroll
            for (int i = 0; i < 4; i++) { float d = v[i] - mu; q += d * d; }
#pragma unroll
            for (int o = 16; o; o >>= 1) q += __shfl_xor_sync(~0u, q, o);
            float rsd = rsqrtf(q * (1.f / 128.f) + 1e-5f);
#pragma unroll
            for (int i = 0; i < 4; i++) {
                int cc = lane + 32 * i;
                fnout[(size_t)(row0 + r) * 128 + cc] =
                    __float2half_rn((v[i] - mu) * rsd * lng[cc] + lnb[cc]);
            }
        }
    }
}

// ---------------------------------------------------------------------------
// gemm64: CTA 128x64, 8 warps (4m x 2n, warp 32x32, acc=32 regs), 3 CTAs/SM.
// ---------------------------------------------------------------------------
#define STG64 27648           // A 128*144 + B 64*144
#define SM64_BYTES (2*STG64)  // 55296 (>= 128*65*4 = 33280 NCHW staging)

template <int EPI>
__global__ void __launch_bounds__(256, 3)
gemm64(const __half* __restrict__ A, int lda,
       const __half* __restrict__ Wt, int K,
       void* __restrict__ Cpv, int ldc,
       const float* __restrict__ p0, const float* __restrict__ p1,
       const float* __restrict__ p2, const float* __restrict__ p3,
       const float* __restrict__ Rs, int ldr) {
    extern __shared__ __align__(16) char smem[];
    const u32 sb = smem_u32(smem);
    const int tid = threadIdx.x, wid = tid >> 5, lane = tid & 31;
    const int wm = (wid >> 1) * 32, wn = (wid & 1) * 32;
    const int g = lane >> 2, t2 = lane & 3;
    const int row0 = blockIdx.x * 128, col0 = blockIdx.y * 64;
    const int lrow = tid >> 3, lc8 = tid & 7;

    float acc[2][4][4];
#pragma unroll
    for (int i = 0; i < 2; i++)
#pragma unroll
        for (int j = 0; j < 4; j++)
#pragma unroll
            for (int q = 0; q < 4; q++) acc[i][j][q] = 0.f;

    const int nch = K >> 6;
    auto issue = [&](int c) {
        u32 ab = sb + (c & 1) * STG64;
        u32 bb = ab + 18432;
        const __half* Ag = A  + (size_t)row0 * lda + c * 64;
        const __half* Bg = Wt + (size_t)col0 * K   + c * 64;
#pragma unroll
        for (int i = 0; i < 4; i++) {
            int r = i * 32 + lrow;
            cp16(ab + r * 144 + lc8 * 16, Ag + (size_t)r * lda + lc8 * 8);
        }
#pragma unroll
        for (int i = 0; i < 2; i++) {
            int r = i * 32 + lrow;
            cp16(bb + r * 144 + lc8 * 16, Bg + (size_t)r * K + lc8 * 8);
        }
    };

    issue(0);
    asm volatile("cp.async.commit_group;");
    for (int c = 0; c < nch; c++) {
        if (c + 1 < nch) {
            issue(c + 1);
            asm volatile("cp.async.commit_group;");
            asm volatile("cp.async.wait_group 1;");
        } else {
            asm volatile("cp.async.wait_group 0;");
        }
        __syncthreads();
        u32 ab = sb + (c & 1) * STG64;
        u32 bb = ab + 18432;
#pragma unroll
        for (int kb = 0; kb < 4; kb++) {
            u32 a[2][4], b[4][2];
#pragma unroll
            for (int mf = 0; mf < 2; mf++) {
                int r = wm + mf * 16 + (lane & 7) + ((lane >> 3) & 1) * 8;
                ldm_x4(a[mf][0], a[mf][1], a[mf][2], a[mf][3],
                       ab + r * 144 + kb * 32 + (lane >> 4) * 16);
            }
#pragma unroll
            for (int np = 0; np < 2; np++) {
                int r = wn + np * 16 + (lane & 7) + ((lane >> 4) & 1) * 8;
                ldm_x4(b[2*np][0], b[2*np][1], b[2*np+1][0], b[2*np+1][1],
                       bb + r * 144 + kb * 32 + ((lane >> 3) & 1) * 16);
            }
#pragma unroll
            for (int mf = 0; mf < 2; mf++)
#pragma unroll
                for (int nf = 0; nf < 4; nf++)
                    mma_fp16(acc[mf][nf], a[mf], b[nf]);
        }
        __syncthreads();
    }

    if constexpr (EPI == EPI_NCHW) {
        float* stg = (float*)smem;   // 128 x 65
#pragma unroll
        for (int mf = 0; mf < 2; mf++)
#pragma unroll
            for (int nf = 0; nf < 4; nf++) {
                int r = wm + mf * 16 + g;
                int cl = wn + nf * 8 + t2 * 2;
                stg[r * 65 + cl]           = acc[mf][nf][0];
                stg[r * 65 + cl + 1]       = acc[mf][nf][1];
                stg[(r + 8) * 65 + cl]     = acc[mf][nf][2];
                stg[(r + 8) * 65 + cl + 1] = acc[mf][nf][3];
            }
        __syncthreads();
        float* Cp = (float*)Cpv;
        for (int it = 0; it < 32; it++) {
            int idx  = it * 256 + tid;
            int lcol = idx >> 7;
            int r    = idx & 127;
            int col  = col0 + lcol;
            int row  = row0 + r;
            float v  = stg[r * 65 + lcol];
            float sc = p0[col] * rsqrtf(p3[col] + 1e-5f);
            v = v * sc + (p1[col] - p2[col] * sc);
            v = v / (1.f + __expf(-v));
            Cp[(((size_t)(row >> 12)) * C2_ + col) * 4096 + (row & 4095)] = v;
        }
    } else {
#pragma unroll
        for (int mf = 0; mf < 2; mf++) {
#pragma unroll
            for (int nf = 0; nf < 4; nf++) {
                int col = col0 + wn + nf * 8 + t2 * 2;
                float e0 = p0[col], e1 = p0[col + 1];
#pragma unroll
                for (int h = 0; h < 2; h++) {
                    int row = row0 + wm + mf * 16 + g + h * 8;
                    float v0 = acc[mf][nf][h * 2];
                    float v1 = acc[mf][nf][h * 2 + 1];
                    if constexpr (EPI == EPI_QKV) {
                        v0 += e0; v1 += e1;
                    } else if constexpr (EPI == EPI_GELU) {
                        v0 += e0; v1 += e1;
                        v0 = 0.5f * v0 * (1.f + erff(v0 * 0.70710678118654752f));
                        v1 = 0.5f * v1 * (1.f + erff(v1 * 0.70710678118654752f));
                    } else if constexpr (EPI == EPI_FFN2) {
                        float2 rs = *(const float2*)(Rs + (size_t)row * ldr + col);
                        v0 = v0 + e0 + rs.x;
                        v1 = v1 + e1 + rs.y;
                    }
                    *(__half2*)((__half*)Cpv + (size_t)row * ldc + col) =
                        __floats2half2_rn(v0, v1);
                }
            }
        }
    }
}

// ---------------------------------------------------------------------------
// Tensor-core retention attention. One warp per (b, head, fixed line).
// ---------------------------------------------------------------------------
template <int PASS>
__global__ void __launch_bounds__(128)
attn_mma(const __half* __restrict__ qkv,
         float* __restrict__ partial,
         __half* __restrict__ out16) {
    __shared__ __half sQ[4][64 * 24];
    __shared__ __half sK[4][64 * 24];
    __shared__ __half sV[4][64 * 24];
    __shared__ float decrow[64];

    const int tid = threadIdx.x, wid = tid >> 5, lane = tid & 31;
    const int g = lane >> 2, t2 = lane & 3;
    const int fixed = blockIdx.x * 4 + wid;
    const int n = blockIdx.y, b = blockIdx.z;

    if (tid < 64) {
        float dec = logf(1.f - exp2f(-2.f - 0.5f * (float)n));
        decrow[tid] = 0.5f * __expf(dec * (float)tid);
    }

#pragma unroll
    for (int tt = 0; tt < 2; tt++) {
        int t = lane + tt * 32;
        size_t tok = (PASS == 0) ? ((size_t)(b * 64 + t) * 64 + fixed)
                                 : ((size_t)(b * 64 + fixed) * 64 + t);
        const uint4* src = (const uint4*)(qkv + tok * 384 + n * HD_);
        *(uint4*)&sQ[wid][t * 24]     = src[0];
        *(uint4*)&sQ[wid][t * 24 + 8] = src[1];
        *(uint4*)&sK[wid][t * 24]     = src[16];
        *(uint4*)&sK[wid][t * 24 + 8] = src[17];
        *(uint4*)&sV[wid][t * 24]     = src[32];
        *(uint4*)&sV[wid][t * 24 + 8] = src[33];
    }
    __syncthreads();

    const u32 qb = smem_u32(&sQ[wid][0]);
    const u32 kb = smem_u32(&sK[wid][0]);
    const u32 vb = smem_u32(&sV[wid][0]);

    u32 qa[4][4];
#pragma unroll
    for (int mf = 0; mf < 4; mf++) {
        int r = mf * 16 + (lane & 7) + ((lane >> 3) & 1) * 8;
        ldm_x4(qa[mf][0], qa[mf][1], qa[mf][2], qa[mf][3],
               qb + r * 48 + (lane >> 4) * 16);
    }

    float oacc[4][2][4];
#pragma unroll
    for (int i = 0; i < 4; i++)
#pragma unroll
        for (int j = 0; j < 2; j++)
#pragma unroll
            for (int q = 0; q < 4; q++) oacc[i][j][q] = 0.f;

#pragma unroll
    for (int jb = 0; jb < 4; jb++) {
        u32 kf[4];
        {
            int r = jb * 16 + (lane & 7) + ((lane >> 4) & 1) * 8;
            ldm_x4(kf[0], kf[1], kf[2], kf[3],
                   kb + r * 48 + ((lane >> 3) & 1) * 16);
        }
        float s[4][2][4];
#pragma unroll
        for (int mf = 0; mf < 4; mf++)
#pragma unroll
            for (int np = 0; np < 2; np++) {
#pragma unroll
                for (int q = 0; q < 4; q++) s[mf][np][q] = 0.f;
                u32 bfrag[2] = { kf[2 * np], kf[2 * np + 1] };
                mma_fp16(s[mf][np], qa[mf], bfrag);
            }
        u32 aP[4][4];
#pragma unroll
        for (int mf = 0; mf < 4; mf++) {
#pragma unroll
            for (int np = 0; np < 2; np++) {
                int i0 = mf * 16 + g;
                int j0 = jb * 16 + np * 8 + t2 * 2;
                int d00 = i0 - j0;       d00 = d00 < 0 ? -d00 : d00;
                int d01 = i0 - j0 - 1;   d01 = d01 < 0 ? -d01 : d01;
                int d10 = i0 + 8 - j0;   d10 = d10 < 0 ? -d10 : d10;
                int d11 = i0 + 7 - j0;   d11 = d11 < 0 ? -d11 : d11;
                s[mf][np][0] *= decrow[d00];
                s[mf][np][1] *= decrow[d01];
                s[mf][np][2] *= decrow[d10];
                s[mf][np][3] *= decrow[d11];
            }
            __half2 h;
            h = __floats2half2_rn(s[mf][0][0], s[mf][0][1]); aP[mf][0] = *(u32*)&h;
            h = __floats2half2_rn(s[mf][0][2], s[mf][0][3]); aP[mf][1] = *(u32*)&h;
            h = __floats2half2_rn(s[mf][1][0], s[mf][1][1]); aP[mf][2] = *(u32*)&h;
            h = __floats2half2_rn(s[mf][1][2], s[mf][1][3]); aP[mf][3] = *(u32*)&h;
        }
        u32 vf[4];
        {
            int r = jb * 16 + (lane & 7) + ((lane >> 3) & 1) * 8;
            ldm_x4t(vf[0], vf[1], vf[2], vf[3],
                    vb + r * 48 + (lane >> 4) * 16);
        }
#pragma unroll
        for (int mf = 0; mf < 4; mf++)
#pragma unroll
            for (int np = 0; np < 2; np++) {
                u32 bfrag[2] = { vf[2 * np], vf[2 * np + 1] };
                mma_fp16(oacc[mf][np], aP[mf], bfrag);
            }
    }

#pragma unroll
    for (int mf = 0; mf < 4; mf++)
#pragma unroll
        for (int np = 0; np < 2; np++) {
            int ch = n * HD_ + np * 8 + t2 * 2;
#pragma unroll
            for (int h = 0; h < 2; h++) {
                int i = mf * 16 + g + h * 8;
                size_t tok = (PASS == 0) ? ((size_t)(b * 64 + i) * 64 + fixed)
                                         : ((size_t)(b * 64 + fixed) * 64 + i);
                float v0 = oacc[mf][np][h * 2];
                float v1 = oacc[mf][np][h * 2 + 1];
                if (PASS == 0) {
                    *(float2*)(partial + tok * 128 + ch) = make_float2(v0, v1);
                } else {
                    float2 pr = *(const float2*)(partial + tok * 128 + ch);
                    *(__half2*)(out16 + tok * 128 + ch) =
                        __floats2half2_rn(pr.x + v0, pr.y + v1);
                }
            }
        }
}

// ---------------------------------------------------------------------------
extern "C" void kernel_launch(void* const* d_in, const int* in_sizes, int n_in,
                              void* d_out, int out_size) {
    const float* x      = (const float*)d_in[0];
    const float* cv1_w  = (const float*)d_in[1];
    const float* bn1_g  = (const float*)d_in[2];
    const float* bn1_b  = (const float*)d_in[3];
    const float* bn1_m  = (const float*)d_in[4];
    const float* bn1_v  = (const float*)d_in[5];
    const float* cv2_w  = (const float*)d_in[6];
    const float* bn2_g  = (const float*)d_in[7];
    const float* bn2_b  = (const float*)d_in[8];
    const float* bn2_m  = (const float*)d_in[9];
    const float* bn2_v  = (const float*)d_in[10];
    const float* ln1_g  = (const float*)d_in[11];
    const float* ln1_b  = (const float*)d_in[12];
    const float* qkv_w  = (const float*)d_in[13];
    const float* qkv_b  = (const float*)d_in[14];
    const float* proj_w = (const float*)d_in[15];
    const float* proj_b = (const float*)d_in[16];
    const float* gamma  = (const float*)d_in[17];
    const float* ln2_g  = (const float*)d_in[18];
    const float* ln2_b  = (const float*)d_in[19];
    const float* ffn_w1 = (const float*)d_in[20];
    const float* ffn_b1 = (const float*)d_in[21];
    const float* ffn_w2 = (const float*)d_in[22];
    const float* ffn_b2 = (const float*)d_in[23];
    float* out = (float*)d_out;

    __half *xt16, *cat16, *fn16, *qkv16, *attn16, *h116, *w16;
    float *y2f, *attnp, *f2;
    cudaGetSymbolAddress((void**)&xt16,   g_xt16);
    cudaGetSymbolAddress((void**)&cat16,  g_cat16);
    cudaGetSymbolAddress((void**)&y2f,    g_y2f);
    cudaGetSymbolAddress((void**)&fn16,   g_fn16);
    cudaGetSymbolAddress((void**)&qkv16,  g_qkv16);
    cudaGetSymbolAddress((void**)&attnp,  g_attnp);
    cudaGetSymbolAddress((void**)&attn16, g_attn16);
    cudaGetSymbolAddress((void**)&f2,     g_f2);
    cudaGetSymbolAddress((void**)&h116,   g_h116);
    cudaGetSymbolAddress((void**)&w16,    g_w16);

    __half* w_cv1  = w16;
    __half* w_qkv  = w_cv1 + 65536;
    __half* w_proj = w_qkv + 49152;
    __half* w_f1   = w_proj + 16384;
    __half* w_f2   = w_f1 + 32768;
    __half* w_cv2  = w_f2 + 32768;

    cudaFuncSetAttribute(gemm128<EPI_CV1>,  cudaFuncAttributeMaxDynamicSharedMemorySize, SM128_BYTES);
    cudaFuncSetAttribute(gemm128<EPI_PROJ>, cudaFuncAttributeMaxDynamicSharedMemorySize, SM128_BYTES);
    cudaFuncSetAttribute(gemm64<EPI_QKV>,   cudaFuncAttributeMaxDynamicSharedMemorySize, SM64_BYTES);
    cudaFuncSetAttribute(gemm64<EPI_GELU>,  cudaFuncAttributeMaxDynamicSharedMemorySize, SM64_BYTES);
    cudaFuncSetAttribute(gemm64<EPI_FFN2>,  cudaFuncAttributeMaxDynamicSharedMemorySize, SM64_BYTES);
    cudaFuncSetAttribute(gemm64<EPI_NCHW>,  cudaFuncAttributeMaxDynamicSharedMemorySize, SM64_BYTES);

    // 0) weights -> fp16
    convert_w_all<<<dim3(192, 6), 256>>>(cv1_w, qkv_w, proj_w, ffn_w1, ffn_w2,
                                         cv2_w, w16);

    // 1) x NCHW -> xt16
    transpose_x_kernel<<<dim3(HW_/32, C1_/32, B_), dim3(32, 8)>>>(x, xt16);

    // 2) cv1 + BN + SiLU -> cat16[:,0:256] (+ y2f, + fused LN1 -> fn16)
    gemm128<EPI_CV1><<<dim3(TOKENS/128, 2), 256, SM128_BYTES>>>(
        xt16, 256, w_cv1, 256, cat16, 384, bn1_g, bn1_b, bn1_m, bn1_v,
        nullptr, 0, ln1_g, ln1_b, fn16);

    // 3) qkv
    gemm64<EPI_QKV><<<dim3(TOKENS/128, 6), 256, SM64_BYTES>>>(
        fn16, 128, w_qkv, 128, qkv16, 384, qkv_b, nullptr, nullptr, nullptr,
        nullptr, 0);

    // 4) attention H then W
    attn_mma<0><<<dim3(16, NH_, B_), 128>>>(qkv16, attnp, attn16);
    attn_mma<1><<<dim3(16, NH_, B_), 128>>>(qkv16, attnp, attn16);

    // 5) proj (+res y2, *gamma) -> f2 (+ fused LN2 -> fn16)
    gemm128<EPI_PROJ><<<dim3(TOKENS/128, 1), 256, SM128_BYTES>>>(
        attn16, 128, w_proj, 128, f2, 128, proj_b, gamma, nullptr, nullptr,
        y2f, 128, ln2_g, ln2_b, fn16);

    // 6) ffn1 + GELU
    gemm64<EPI_GELU><<<dim3(TOKENS/128, 4), 256, SM64_BYTES>>>(
        fn16, 128, w_f1, 128, h116, 256, ffn_b1, nullptr, nullptr, nullptr,
        nullptr, 0);

    // 7) ffn2 + bias + res f2 -> cat16[:,256:384]
    gemm64<EPI_FFN2><<<dim3(TOKENS/128, 2), 256, SM64_BYTES>>>(
        h116, 256, w_f2, 256, cat16 + 256, 384, ffn_b2, nullptr, nullptr, nullptr,
        f2, 128);

    // 8) cv2 + BN + SiLU -> NCHW out
    gemm64<EPI_NCHW><<<dim3(TOKENS/128, 4), 256, SM64_BYTES>>>(
        cat16, 384, w_cv2, 384, out, 0, bn2_g, bn2_b, bn2_m, bn2_v,
        nullptr, 0);
}